// round 11
// baseline (speedup 1.0000x reference)
#include <cuda_runtime.h>
#include <cstdint>
#include <math.h>

#define NTOK 8192
#define DIM  1024
#define HID  256
#define HIDC 128
#define POOL 16384
#define TOPK 1024
#define NCHUNK 8
#define TOKC (NTOK / NCHUNK)     // 1024 tokens per chunk

// ---------------- scratch (device globals: no allocations allowed) ----------
__device__ float g_hs[NTOK * HID];                              // 8 MB
__device__ float g_hc[NTOK * HIDC];                             // 4 MB
__device__ float g_scores[(size_t)NTOK * POOL];                 // 512 MB
__device__ int   g_budget[NTOK];

// packed fp32x2 FMA (sm_100+): two independent rn-rounded fp32 FMAs per issue.
__device__ __forceinline__ float2 ffma2(float2 a, float2 b, float2 c) {
    unsigned long long A = *(unsigned long long*)&a;
    unsigned long long B = *(unsigned long long*)&b;
    unsigned long long C = *(unsigned long long*)&c;
    unsigned long long D;
    asm("fma.rn.f32x2 %0, %1, %2, %3;" : "=l"(D) : "l"(A), "l"(B), "l"(C));
    return *(float2*)&D;
}

// ---------------- fp32x2 GEMM core (proven R2 version) ----------------------
template<bool RELU>
__device__ __forceinline__ void gemm_body(const float* __restrict__ A,
                                          const float* __restrict__ B,
                                          const float* __restrict__ bias,
                                          float* __restrict__ C,
                                          int N, int K, int bm, int bn,
                                          float Asm[2][8][128], float Bsm[2][8][128])
{
    const int tid = threadIdx.x;
    const int tx  = tid & 15;
    const int ty  = tid >> 4;

    float2 acc[8][4];
#pragma unroll
    for (int i = 0; i < 8; i++)
#pragma unroll
        for (int q = 0; q < 4; q++) acc[i][q] = make_float2(0.f, 0.f);

    const int ar = tid >> 1;
    const int ac = (tid & 1) * 4;
    const int br = tid >> 5;
    const int bc = (tid & 31) * 4;
    const float* Aptr = A + (size_t)(bm + ar) * K + ac;
    const float* Bptr = B + (size_t)br * N + bn + bc;

    const int NT = K >> 3;

    float4 av = *(const float4*)(Aptr);
    float4 bv = *(const float4*)(Bptr);
    Asm[0][ac + 0][ar] = av.x; Asm[0][ac + 1][ar] = av.y;
    Asm[0][ac + 2][ar] = av.z; Asm[0][ac + 3][ar] = av.w;
    *(float4*)&Bsm[0][br][bc] = bv;
    __syncthreads();

    for (int t = 0; t < NT; t++) {
        const int buf = t & 1;
        const bool more = (t + 1) < NT;
        if (more) {
            av = *(const float4*)(Aptr + (t + 1) * 8);
            bv = *(const float4*)(Bptr + (size_t)(t + 1) * 8 * N);
        }

#pragma unroll
        for (int k = 0; k < 8; k++) {
            float4 a0 = *(const float4*)&Asm[buf][k][ty * 8];
            float4 a1 = *(const float4*)&Asm[buf][k][ty * 8 + 4];
            float4 b0 = *(const float4*)&Bsm[buf][k][tx * 4];
            float4 b1 = *(const float4*)&Bsm[buf][k][tx * 4 + 64];
            float2 bp[4];
            bp[0] = make_float2(b0.x, b0.y); bp[1] = make_float2(b0.z, b0.w);
            bp[2] = make_float2(b1.x, b1.y); bp[3] = make_float2(b1.z, b1.w);
            float a[8] = {a0.x, a0.y, a0.z, a0.w, a1.x, a1.y, a1.z, a1.w};
#pragma unroll
            for (int i = 0; i < 8; i++) {
                float2 ad = make_float2(a[i], a[i]);
#pragma unroll
                for (int q = 0; q < 4; q++)
                    acc[i][q] = ffma2(ad, bp[q], acc[i][q]);
            }
        }

        if (more) {
            const int nb = buf ^ 1;
            Asm[nb][ac + 0][ar] = av.x; Asm[nb][ac + 1][ar] = av.y;
            Asm[nb][ac + 2][ar] = av.z; Asm[nb][ac + 3][ar] = av.w;
            *(float4*)&Bsm[nb][br][bc] = bv;
        }
        __syncthreads();
    }

#pragma unroll
    for (int i = 0; i < 8; i++) {
        const int row = bm + ty * 8 + i;
#pragma unroll
        for (int g = 0; g < 2; g++) {
            const int col = bn + tx * 4 + g * 64;
            float4 v;
            v.x = acc[i][g * 2 + 0].x + bias[col + 0];
            v.y = acc[i][g * 2 + 0].y + bias[col + 1];
            v.z = acc[i][g * 2 + 1].x + bias[col + 2];
            v.w = acc[i][g * 2 + 1].y + bias[col + 3];
            if (RELU) {
                v.x = fmaxf(v.x, 0.f); v.y = fmaxf(v.y, 0.f);
                v.z = fmaxf(v.z, 0.f); v.w = fmaxf(v.w, 0.f);
            }
            *(float4*)(C + (size_t)row * N + col) = v;
        }
    }
}

__global__ void __launch_bounds__(256, 2)
sgemm2_bias(const float* __restrict__ A, const float* __restrict__ B,
            const float* __restrict__ bias, float* __restrict__ C,
            int N, int K)
{
    __shared__ float As[2][8][128];
    __shared__ float Bs[2][8][128];
    gemm_body<false>(A, B, bias, C, N, K, blockIdx.y * 128, blockIdx.x * 128, As, Bs);
}

__global__ void __launch_bounds__(256, 2)
small_gemms(const float* __restrict__ x,
            const float* __restrict__ ws1, const float* __restrict__ bs1,
            const float* __restrict__ w1c, const float* __restrict__ b1c,
            float* __restrict__ hs, float* __restrict__ hc)
{
    __shared__ float As[2][8][128];
    __shared__ float Bs[2][8][128];
    const int bx = blockIdx.x;
    if (bx < 2)
        gemm_body<true>(x, ws1, bs1, hs, HID,  DIM, blockIdx.y * 128, bx * 128, As, Bs);
    else
        gemm_body<true>(x, w1c, b1c, hc, HIDC, DIM, blockIdx.y * 128, 0, As, Bs);
}

// ---------------- complexity -> sigmoid -> budget ---------------------------
__global__ void complexity_kernel(const float* __restrict__ hc,
                                  const float* __restrict__ w2c,
                                  const float* __restrict__ b2c,
                                  float* __restrict__ out_c,
                                  int* __restrict__ budget)
{
    int warp = (blockIdx.x * blockDim.x + threadIdx.x) >> 5;
    int lane = threadIdx.x & 31;
    if (warp >= NTOK) return;
    const float* h = hc + (size_t)warp * HIDC;
    float s = 0.f;
#pragma unroll
    for (int i = lane; i < HIDC; i += 32) s += h[i] * w2c[i];
#pragma unroll
    for (int o = 16; o; o >>= 1) s += __shfl_xor_sync(0xFFFFFFFFu, s, o);
    if (lane == 0) {
        float z = s + b2c[0];
        float c = 1.f / (1.f + expf(-z));
        out_c[warp] = c;
        float raw = 100.f + 924.f * (c * c);
        raw = fminf(fmaxf(raw, 100.f), 1024.f);
        budget[warp] = (int)rintf(raw);
    }
}

// ---------------- top-k helpers ---------------------------------------------
__device__ __forceinline__ uint32_t f2mk(float f) {
    uint32_t u = __float_as_uint(f);
    return (u & 0x80000000u) ? ~u : (u | 0x80000000u);
}
__device__ __forceinline__ float mk2f(uint32_t mk) {
    uint32_t u = (mk & 0x80000000u) ? (mk ^ 0x80000000u) : ~mk;
    return __uint_as_float(u);
}

// ---------------- fused top-k: threshold select + counting sort -------------
// (identical to R10; pointers pre-offset per chunk by the launcher)
__global__ void __launch_bounds__(512, 2)
topk_kernel(const float* __restrict__ scores, const int* __restrict__ budget,
            float* __restrict__ out_idx, float* __restrict__ out_w,
            float* __restrict__ out_m)
{
    extern __shared__ char smem_raw[];
    unsigned long long* staging = (unsigned long long*)smem_raw;
    unsigned long long* fin     = staging + 2048;
    uint32_t* hist     = (uint32_t*)(fin + 2048);
    uint32_t* chunksum = hist + 4096;
    uint32_t* warp_aux = chunksum + 256;
    float*    s_red    = (float*)(warp_aux + 32);
    uint32_t* s_redu   = (uint32_t*)s_red;
    uint32_t* scal     = (uint32_t*)(s_red + 512);
    #define S_BSTAR scal[0]
    #define S_CNT   scal[1]

    const int t    = blockIdx.x;
    const int tid  = threadIdx.x;
    const int lane = tid & 31;
    const int wid  = tid >> 5;
    const float4* row4 = (const float4*)(scores + (size_t)t * POOL);

    uint32_t cnt = 0, bstar = 0;
    bool     use_sample = true;
    uint32_t target = 192;

    for (int attempt = 0; attempt < 2; attempt++) {
        for (int i = tid; i < 4096; i += 512) hist[i] = 0;
        __syncthreads();

        if (use_sample) {
            float4 v = row4[tid];
            atomicAdd(&hist[f2mk(v.x) >> 20], 1u);
            atomicAdd(&hist[f2mk(v.y) >> 20], 1u);
            atomicAdd(&hist[f2mk(v.z) >> 20], 1u);
            atomicAdd(&hist[f2mk(v.w) >> 20], 1u);
        } else {
#pragma unroll
            for (int s = 0; s < 8; s++) {
                float4 v = row4[tid + s * 512];
                atomicAdd(&hist[f2mk(v.x) >> 20], 1u);
                atomicAdd(&hist[f2mk(v.y) >> 20], 1u);
                atomicAdd(&hist[f2mk(v.z) >> 20], 1u);
                atomicAdd(&hist[f2mk(v.w) >> 20], 1u);
            }
        }
        __syncthreads();

        {
            uint32_t v = 0;
            if (tid < 256) {
                uint32_t cs = 0;
#pragma unroll
                for (int b = tid * 16; b < tid * 16 + 16; b++) cs += hist[b];
                v = cs;
#pragma unroll
                for (int o = 1; o < 32; o <<= 1) {
                    uint32_t u = __shfl_down_sync(0xFFFFFFFFu, v, o);
                    if (lane + o < 32) v += u;
                }
                if (lane == 0) warp_aux[wid] = v;
            }
            __syncthreads();
            if (tid < 8) {
                uint32_t w = warp_aux[tid];
                uint32_t incl = w;
#pragma unroll
                for (int o = 1; o < 8; o <<= 1) {
                    uint32_t u = __shfl_down_sync(0xFFu, incl, o);
                    if (tid + o < 8) incl += u;
                }
                warp_aux[8 + tid] = incl - w;
            }
            __syncthreads();
            if (tid < 256) chunksum[tid] = v + warp_aux[8 + wid];
            __syncthreads();
        }

        if (tid < 256) {
            uint32_t Sc = chunksum[tid];
            uint32_t Sn = (tid < 255) ? chunksum[tid + 1] : 0;
            if (Sc >= target && Sn < target) {
                uint32_t cum = Sn;
                int b;
                for (b = tid * 16 + 15; b > tid * 16; b--) {
                    cum += hist[b];
                    if (cum >= target) break;
                }
                S_BSTAR = (uint32_t)b;
            }
        }
        __syncthreads();
        bstar = S_BSTAR;

        for (int i = tid; i < 4096; i += 512) hist[i] = 0;
        __syncthreads();

        uint32_t c = 0;
#pragma unroll
        for (int h = 0; h < 2; h++) {
            float4 vv[4];
#pragma unroll
            for (int s = 0; s < 4; s++) vv[s] = row4[tid + (h * 4 + s) * 512];
#pragma unroll
            for (int s = 0; s < 4; s++) {
                c += ((f2mk(vv[s].x) >> 20) >= bstar);
                c += ((f2mk(vv[s].y) >> 20) >= bstar);
                c += ((f2mk(vv[s].z) >> 20) >= bstar);
                c += ((f2mk(vv[s].w) >> 20) >= bstar);
            }
        }
        uint32_t incl = c;
#pragma unroll
        for (int o = 1; o < 32; o <<= 1) {
            uint32_t u = __shfl_up_sync(0xFFFFFFFFu, incl, o);
            if (lane >= o) incl += u;
        }
        const uint32_t excl = incl - c;
        if (lane == 31) warp_aux[wid] = incl;
        __syncthreads();
        if (tid < 16) {
            uint32_t w = warp_aux[tid];
            uint32_t wi = w;
#pragma unroll
            for (int o = 1; o < 16; o <<= 1) {
                uint32_t u = __shfl_up_sync(0xFFFFu, wi, o);
                if (tid >= o) wi += u;
            }
            warp_aux[16 + tid] = wi - w;
            if (tid == 15) S_CNT = wi;
        }
        __syncthreads();
        cnt = S_CNT;

        uint32_t pos = warp_aux[16 + wid] + excl;
#pragma unroll
        for (int h = 0; h < 2; h++) {
            float4 vv[4];
#pragma unroll
            for (int s = 0; s < 4; s++) vv[s] = row4[tid + (h * 4 + s) * 512];
#pragma unroll
            for (int s = 0; s < 4; s++) {
                const int i4 = tid + (h * 4 + s) * 512;
                float vals[4] = {vv[s].x, vv[s].y, vv[s].z, vv[s].w};
#pragma unroll
                for (int e = 0; e < 4; e++) {
                    uint32_t mk = f2mk(vals[e]);
                    if ((mk >> 20) >= bstar) {
                        if (pos < 2048u) {
                            uint32_t idx = (uint32_t)(i4 * 4 + e);
                            staging[pos] = ((unsigned long long)mk << 32) |
                                           (unsigned long long)(0xFFFFFFFFu - idx);
                            uint32_t rel = mk - (bstar << 20);
                            uint32_t fb  = rel >> 13;
                            if (fb > 4095u) fb = 4095u;
                            atomicAdd(&hist[fb], 1u);
                        }
                        pos++;
                    }
                }
            }
        }
        __syncthreads();
        if (cnt >= (uint32_t)TOPK && cnt <= 2048u) break;
        use_sample = false;
        target = TOPK;
        __syncthreads();
    }
    if (cnt > 2048u) cnt = 2048u;

    {
        uint32_t v = 0;
        if (tid < 256) {
            uint32_t cs = 0;
#pragma unroll
            for (int b = tid * 16; b < tid * 16 + 16; b++) cs += hist[b];
            v = cs;
#pragma unroll
            for (int o = 1; o < 32; o <<= 1) {
                uint32_t u = __shfl_down_sync(0xFFFFFFFFu, v, o);
                if (lane + o < 32) v += u;
            }
            if (lane == 0) warp_aux[wid] = v;
        }
        __syncthreads();
        if (tid < 8) {
            uint32_t w = warp_aux[tid];
            uint32_t incl2 = w;
#pragma unroll
            for (int o = 1; o < 8; o <<= 1) {
                uint32_t u = __shfl_down_sync(0xFFu, incl2, o);
                if (tid + o < 8) incl2 += u;
            }
            warp_aux[8 + tid] = incl2 - w;
        }
        __syncthreads();
        if (tid < 256) chunksum[tid] = v + warp_aux[8 + wid];
        __syncthreads();
    }
    if (tid < 256) {
        uint32_t acc = (tid < 255) ? chunksum[tid + 1] : 0;
        for (int b = tid * 16 + 15; b >= tid * 16; b--) {
            uint32_t c2 = hist[b];
            hist[b] = acc;
            acc += c2;
        }
    }
    __syncthreads();

    {
        uint32_t lmin = cnt;
#pragma unroll
        for (int s = 0; s < 8; s++) {
            uint32_t b = hist[tid + s * 512];
            if (b >= (uint32_t)TOPK && b < lmin) lmin = b;
        }
        s_redu[tid] = lmin;
        __syncthreads();
        for (int o = 256; o; o >>= 1) {
            if (tid < o) {
                uint32_t a = s_redu[tid], b = s_redu[tid + o];
                s_redu[tid] = (b < a) ? b : a;
            }
            __syncthreads();
        }
    }
    const int end = (int)s_redu[0];
    __syncthreads();

    for (int i = tid; i < (int)cnt; i += 512) {
        unsigned long long k = staging[i];
        uint32_t mk  = (uint32_t)(k >> 32);
        uint32_t rel = mk - (bstar << 20);
        uint32_t fb  = rel >> 13;
        if (fb > 4095u) fb = 4095u;
        if (hist[fb] < (uint32_t)end) {
            uint32_t p = atomicAdd(&hist[fb], 1u);
            fin[p] = k;
        }
    }
    __syncthreads();

    while (true) {
        int moved = 0;
#pragma unroll
        for (int r = 0; r < 2; r++) {
            int i = tid + r * 512;
            int p = 2 * i;
            if (p + 1 < end) {
                unsigned long long a = fin[p], b = fin[p + 1];
                if (a < b) { fin[p] = b; fin[p + 1] = a; moved = 1; }
            }
        }
        __syncthreads();
#pragma unroll
        for (int r = 0; r < 2; r++) {
            int i = tid + r * 512;
            int p = 2 * i + 1;
            if (p + 1 < end) {
                unsigned long long a = fin[p], b = fin[p + 1];
                if (a < b) { fin[p] = b; fin[p + 1] = a; moved = 1; }
            }
        }
        if (!__syncthreads_or(moved)) break;
    }

    const float vmax = mk2f((uint32_t)(fin[0] >> 32));
    unsigned long long p0 = fin[tid];
    unsigned long long p1 = fin[tid + 512];
    float e0 = expf(mk2f((uint32_t)(p0 >> 32)) - vmax);
    float e1 = expf(mk2f((uint32_t)(p1 >> 32)) - vmax);
    s_red[tid] = e0 + e1;
    __syncthreads();
    for (int o = 256; o; o >>= 1) {
        if (tid < o) s_red[tid] += s_red[tid + o];
        __syncthreads();
    }
    const float inv = 1.f / s_red[0];

    const int bud = budget[t];
    const size_t base = (size_t)t * TOPK;
    {
        uint32_t idx0 = 0xFFFFFFFFu - (uint32_t)(p0 & 0xFFFFFFFFull);
        float m0 = (tid < bud) ? 1.f : 0.f;
        out_idx[base + tid] = (float)idx0;
        out_w[base + tid]   = e0 * inv * m0;
        out_m[base + tid]   = m0;
        uint32_t idx1 = 0xFFFFFFFFu - (uint32_t)(p1 & 0xFFFFFFFFull);
        int jj = tid + 512;
        float m1 = (jj < bud) ? 1.f : 0.f;
        out_idx[base + jj] = (float)idx1;
        out_w[base + jj]   = e1 * inv * m1;
        out_m[base + jj]   = m1;
    }
    #undef S_BSTAR
    #undef S_CNT
}

// ---------------- launch: two-stream chunked pipeline ------------------------
extern "C" void kernel_launch(void* const* d_in, const int* in_sizes, int n_in,
                              void* d_out, int out_size)
{
    const float* x   = (const float*)d_in[0];
    const float* w1c = (const float*)d_in[1];
    const float* b1c = (const float*)d_in[2];
    const float* w2c = (const float*)d_in[3];
    const float* b2c = (const float*)d_in[4];
    const float* ws1 = (const float*)d_in[5];
    const float* bs1 = (const float*)d_in[6];
    const float* ws2 = (const float*)d_in[7];
    const float* bs2 = (const float*)d_in[8];

    float* out     = (float*)d_out;
    float* out_idx = out;
    float* out_w   = out + (size_t)NTOK * TOPK;
    float* out_m   = out + 2 * (size_t)NTOK * TOPK;
    float* out_c   = out + 3 * (size_t)NTOK * TOPK;

    float *hs_p, *hc_p, *sc_p;
    int *bud_p;
    cudaGetSymbolAddress((void**)&hs_p,  g_hs);
    cudaGetSymbolAddress((void**)&hc_p,  g_hc);
    cudaGetSymbolAddress((void**)&sc_p,  g_scores);
    cudaGetSymbolAddress((void**)&bud_p, g_budget);

    const int TOPK_SMEM = 53248;   // 52 KB dynamic

    static bool init_done = false;
    static cudaStream_t sB;
    static cudaEvent_t evG[NCHUNK];
    static cudaEvent_t evJoin;
    if (!init_done) {
        cudaFuncSetAttribute(topk_kernel,
                             cudaFuncAttributeMaxDynamicSharedMemorySize, TOPK_SMEM);
        cudaStreamCreateWithFlags(&sB, cudaStreamNonBlocking);
        for (int i = 0; i < NCHUNK; i++)
            cudaEventCreateWithFlags(&evG[i], cudaEventDisableTiming);
        cudaEventCreateWithFlags(&evJoin, cudaEventDisableTiming);
        init_done = true;
    }

    // stream 0: small GEMMs + complexity
    small_gemms<<<dim3(3, NTOK / 128), 256>>>(x, ws1, bs1, w1c, b1c, hs_p, hc_p);
    complexity_kernel<<<NTOK / 8, 256>>>(hc_p, w2c, b2c, out_c, bud_p);

    // pipelined: GEMM2 chunk c on stream 0; topk chunk c on stream B after evG[c]
    for (int c = 0; c < NCHUNK; c++) {
        const size_t trow = (size_t)c * TOKC;
        sgemm2_bias<<<dim3(POOL / 128, TOKC / 128), 256>>>(
            hs_p + trow * HID, ws2, bs2, sc_p + trow * POOL, POOL, HID);
        cudaEventRecord(evG[c], 0);
        cudaStreamWaitEvent(sB, evG[c], 0);
        topk_kernel<<<TOKC, 512, TOPK_SMEM, sB>>>(
            sc_p + trow * POOL, bud_p + trow,
            out_idx + trow * TOPK, out_w + trow * TOPK, out_m + trow * TOPK);
    }
    // join stream B back into stream 0
    cudaEventRecord(evJoin, sB);
    cudaStreamWaitEvent(0, evJoin, 0);
}

// round 13
// speedup vs baseline: 1.0281x; 1.0281x over previous
#include <cuda_runtime.h>
#include <cstdint>
#include <math.h>

#define NTOK 8192
#define DIM  1024
#define HID  256
#define HIDC 128
#define POOL 16384
#define TOPK 1024
#define NCHUNK 4
#define TOKC (NTOK / NCHUNK)     // 2048 tokens per chunk

// ---------------- scratch (device globals: no allocations allowed) ----------
__device__ float g_hs[NTOK * HID];                              // 8 MB
__device__ float g_hc[NTOK * HIDC];                             // 4 MB
__device__ float g_scores[(size_t)NTOK * POOL];                 // 512 MB
__device__ int   g_budget[NTOK];

// packed fp32x2 FMA (sm_100+): two independent rn-rounded fp32 FMAs per issue.
__device__ __forceinline__ float2 ffma2(float2 a, float2 b, float2 c) {
    unsigned long long A = *(unsigned long long*)&a;
    unsigned long long B = *(unsigned long long*)&b;
    unsigned long long C = *(unsigned long long*)&c;
    unsigned long long D;
    asm("fma.rn.f32x2 %0, %1, %2, %3;" : "=l"(D) : "l"(A), "l"(B), "l"(C));
    return *(float2*)&D;
}

// ---------------- fp32x2 GEMM core (proven R2 version) ----------------------
template<bool RELU>
__device__ __forceinline__ void gemm_body(const float* __restrict__ A,
                                          const float* __restrict__ B,
                                          const float* __restrict__ bias,
                                          float* __restrict__ C,
                                          int N, int K, int bm, int bn,
                                          float Asm[2][8][128], float Bsm[2][8][128])
{
    const int tid = threadIdx.x;
    const int tx  = tid & 15;
    const int ty  = tid >> 4;

    float2 acc[8][4];
#pragma unroll
    for (int i = 0; i < 8; i++)
#pragma unroll
        for (int q = 0; q < 4; q++) acc[i][q] = make_float2(0.f, 0.f);

    const int ar = tid >> 1;
    const int ac = (tid & 1) * 4;
    const int br = tid >> 5;
    const int bc = (tid & 31) * 4;
    const float* Aptr = A + (size_t)(bm + ar) * K + ac;
    const float* Bptr = B + (size_t)br * N + bn + bc;

    const int NT = K >> 3;

    float4 av = *(const float4*)(Aptr);
    float4 bv = *(const float4*)(Bptr);
    Asm[0][ac + 0][ar] = av.x; Asm[0][ac + 1][ar] = av.y;
    Asm[0][ac + 2][ar] = av.z; Asm[0][ac + 3][ar] = av.w;
    *(float4*)&Bsm[0][br][bc] = bv;
    __syncthreads();

    for (int t = 0; t < NT; t++) {
        const int buf = t & 1;
        const bool more = (t + 1) < NT;
        if (more) {
            av = *(const float4*)(Aptr + (t + 1) * 8);
            bv = *(const float4*)(Bptr + (size_t)(t + 1) * 8 * N);
        }

#pragma unroll
        for (int k = 0; k < 8; k++) {
            float4 a0 = *(const float4*)&Asm[buf][k][ty * 8];
            float4 a1 = *(const float4*)&Asm[buf][k][ty * 8 + 4];
            float4 b0 = *(const float4*)&Bsm[buf][k][tx * 4];
            float4 b1 = *(const float4*)&Bsm[buf][k][tx * 4 + 64];
            float2 bp[4];
            bp[0] = make_float2(b0.x, b0.y); bp[1] = make_float2(b0.z, b0.w);
            bp[2] = make_float2(b1.x, b1.y); bp[3] = make_float2(b1.z, b1.w);
            float a[8] = {a0.x, a0.y, a0.z, a0.w, a1.x, a1.y, a1.z, a1.w};
#pragma unroll
            for (int i = 0; i < 8; i++) {
                float2 ad = make_float2(a[i], a[i]);
#pragma unroll
                for (int q = 0; q < 4; q++)
                    acc[i][q] = ffma2(ad, bp[q], acc[i][q]);
            }
        }

        if (more) {
            const int nb = buf ^ 1;
            Asm[nb][ac + 0][ar] = av.x; Asm[nb][ac + 1][ar] = av.y;
            Asm[nb][ac + 2][ar] = av.z; Asm[nb][ac + 3][ar] = av.w;
            *(float4*)&Bsm[nb][br][bc] = bv;
        }
        __syncthreads();
    }

#pragma unroll
    for (int i = 0; i < 8; i++) {
        const int row = bm + ty * 8 + i;
#pragma unroll
        for (int g = 0; g < 2; g++) {
            const int col = bn + tx * 4 + g * 64;
            float4 v;
            v.x = acc[i][g * 2 + 0].x + bias[col + 0];
            v.y = acc[i][g * 2 + 0].y + bias[col + 1];
            v.z = acc[i][g * 2 + 1].x + bias[col + 2];
            v.w = acc[i][g * 2 + 1].y + bias[col + 3];
            if (RELU) {
                v.x = fmaxf(v.x, 0.f); v.y = fmaxf(v.y, 0.f);
                v.z = fmaxf(v.z, 0.f); v.w = fmaxf(v.w, 0.f);
            }
            *(float4*)(C + (size_t)row * N + col) = v;
        }
    }
}

__global__ void __launch_bounds__(256, 2)
sgemm2_bias(const float* __restrict__ A, const float* __restrict__ B,
            const float* __restrict__ bias, float* __restrict__ C,
            int N, int K)
{
    __shared__ float As[2][8][128];
    __shared__ float Bs[2][8][128];
    gemm_body<false>(A, B, bias, C, N, K, blockIdx.y * 128, blockIdx.x * 128, As, Bs);
}

__global__ void __launch_bounds__(256, 2)
small_gemms(const float* __restrict__ x,
            const float* __restrict__ ws1, const float* __restrict__ bs1,
            const float* __restrict__ w1c, const float* __restrict__ b1c,
            float* __restrict__ hs, float* __restrict__ hc)
{
    __shared__ float As[2][8][128];
    __shared__ float Bs[2][8][128];
    const int bx = blockIdx.x;
    if (bx < 2)
        gemm_body<true>(x, ws1, bs1, hs, HID,  DIM, blockIdx.y * 128, bx * 128, As, Bs);
    else
        gemm_body<true>(x, w1c, b1c, hc, HIDC, DIM, blockIdx.y * 128, 0, As, Bs);
}

// ---------------- complexity -> sigmoid -> budget ---------------------------
__global__ void complexity_kernel(const float* __restrict__ hc,
                                  const float* __restrict__ w2c,
                                  const float* __restrict__ b2c,
                                  float* __restrict__ out_c,
                                  int* __restrict__ budget)
{
    int warp = (blockIdx.x * blockDim.x + threadIdx.x) >> 5;
    int lane = threadIdx.x & 31;
    if (warp >= NTOK) return;
    const float* h = hc + (size_t)warp * HIDC;
    float s = 0.f;
#pragma unroll
    for (int i = lane; i < HIDC; i += 32) s += h[i] * w2c[i];
#pragma unroll
    for (int o = 16; o; o >>= 1) s += __shfl_xor_sync(0xFFFFFFFFu, s, o);
    if (lane == 0) {
        float z = s + b2c[0];
        float c = 1.f / (1.f + expf(-z));
        out_c[warp] = c;
        float raw = 100.f + 924.f * (c * c);
        raw = fminf(fmaxf(raw, 100.f), 1024.f);
        budget[warp] = (int)rintf(raw);
    }
}

// ---------------- top-k helpers ---------------------------------------------
__device__ __forceinline__ uint32_t f2mk(float f) {
    uint32_t u = __float_as_uint(f);
    return (u & 0x80000000u) ? ~u : (u | 0x80000000u);
}
__device__ __forceinline__ float mk2f(uint32_t mk) {
    uint32_t u = (mk & 0x80000000u) ? (mk ^ 0x80000000u) : ~mk;
    return __uint_as_float(u);
}

// ---------------- fused top-k: threshold select + counting sort (R10) -------
__global__ void __launch_bounds__(512, 2)
topk_kernel(const float* __restrict__ scores, const int* __restrict__ budget,
            float* __restrict__ out_idx, float* __restrict__ out_w,
            float* __restrict__ out_m)
{
    extern __shared__ char smem_raw[];
    unsigned long long* staging = (unsigned long long*)smem_raw;
    unsigned long long* fin     = staging + 2048;
    uint32_t* hist     = (uint32_t*)(fin + 2048);
    uint32_t* chunksum = hist + 4096;
    uint32_t* warp_aux = chunksum + 256;
    float*    s_red    = (float*)(warp_aux + 32);
    uint32_t* s_redu   = (uint32_t*)s_red;
    uint32_t* scal     = (uint32_t*)(s_red + 512);
    #define S_BSTAR scal[0]
    #define S_CNT   scal[1]

    const int t    = blockIdx.x;
    const int tid  = threadIdx.x;
    const int lane = tid & 31;
    const int wid  = tid >> 5;
    const float4* row4 = (const float4*)(scores + (size_t)t * POOL);

    uint32_t cnt = 0, bstar = 0;
    bool     use_sample = true;
    uint32_t target = 192;

    for (int attempt = 0; attempt < 2; attempt++) {
        for (int i = tid; i < 4096; i += 512) hist[i] = 0;
        __syncthreads();

        if (use_sample) {
            float4 v = row4[tid];
            atomicAdd(&hist[f2mk(v.x) >> 20], 1u);
            atomicAdd(&hist[f2mk(v.y) >> 20], 1u);
            atomicAdd(&hist[f2mk(v.z) >> 20], 1u);
            atomicAdd(&hist[f2mk(v.w) >> 20], 1u);
        } else {
#pragma unroll
            for (int s = 0; s < 8; s++) {
                float4 v = row4[tid + s * 512];
                atomicAdd(&hist[f2mk(v.x) >> 20], 1u);
                atomicAdd(&hist[f2mk(v.y) >> 20], 1u);
                atomicAdd(&hist[f2mk(v.z) >> 20], 1u);
                atomicAdd(&hist[f2mk(v.w) >> 20], 1u);
            }
        }
        __syncthreads();

        {
            uint32_t v = 0;
            if (tid < 256) {
                uint32_t cs = 0;
#pragma unroll
                for (int b = tid * 16; b < tid * 16 + 16; b++) cs += hist[b];
                v = cs;
#pragma unroll
                for (int o = 1; o < 32; o <<= 1) {
                    uint32_t u = __shfl_down_sync(0xFFFFFFFFu, v, o);
                    if (lane + o < 32) v += u;
                }
                if (lane == 0) warp_aux[wid] = v;
            }
            __syncthreads();
            if (tid < 8) {
                uint32_t w = warp_aux[tid];
                uint32_t incl = w;
#pragma unroll
                for (int o = 1; o < 8; o <<= 1) {
                    uint32_t u = __shfl_down_sync(0xFFu, incl, o);
                    if (tid + o < 8) incl += u;
                }
                warp_aux[8 + tid] = incl - w;
            }
            __syncthreads();
            if (tid < 256) chunksum[tid] = v + warp_aux[8 + wid];
            __syncthreads();
        }

        if (tid < 256) {
            uint32_t Sc = chunksum[tid];
            uint32_t Sn = (tid < 255) ? chunksum[tid + 1] : 0;
            if (Sc >= target && Sn < target) {
                uint32_t cum = Sn;
                int b;
                for (b = tid * 16 + 15; b > tid * 16; b--) {
                    cum += hist[b];
                    if (cum >= target) break;
                }
                S_BSTAR = (uint32_t)b;
            }
        }
        __syncthreads();
        bstar = S_BSTAR;

        for (int i = tid; i < 4096; i += 512) hist[i] = 0;
        __syncthreads();

        uint32_t c = 0;
#pragma unroll
        for (int h = 0; h < 2; h++) {
            float4 vv[4];
#pragma unroll
            for (int s = 0; s < 4; s++) vv[s] = row4[tid + (h * 4 + s) * 512];
#pragma unroll
            for (int s = 0; s < 4; s++) {
                c += ((f2mk(vv[s].x) >> 20) >= bstar);
                c += ((f2mk(vv[s].y) >> 20) >= bstar);
                c += ((f2mk(vv[s].z) >> 20) >= bstar);
                c += ((f2mk(vv[s].w) >> 20) >= bstar);
            }
        }
        uint32_t incl = c;
#pragma unroll
        for (int o = 1; o < 32; o <<= 1) {
            uint32_t u = __shfl_up_sync(0xFFFFFFFFu, incl, o);
            if (lane >= o) incl += u;
        }
        const uint32_t excl = incl - c;
        if (lane == 31) warp_aux[wid] = incl;
        __syncthreads();
        if (tid < 16) {
            uint32_t w = warp_aux[tid];
            uint32_t wi = w;
#pragma unroll
            for (int o = 1; o < 16; o <<= 1) {
                uint32_t u = __shfl_up_sync(0xFFFFu, wi, o);
                if (tid >= o) wi += u;
            }
            warp_aux[16 + tid] = wi - w;
            if (tid == 15) S_CNT = wi;
        }
        __syncthreads();
        cnt = S_CNT;

        uint32_t pos = warp_aux[16 + wid] + excl;
#pragma unroll
        for (int h = 0; h < 2; h++) {
            float4 vv[4];
#pragma unroll
            for (int s = 0; s < 4; s++) vv[s] = row4[tid + (h * 4 + s) * 512];
#pragma unroll
            for (int s = 0; s < 4; s++) {
                const int i4 = tid + (h * 4 + s) * 512;
                float vals[4] = {vv[s].x, vv[s].y, vv[s].z, vv[s].w};
#pragma unroll
                for (int e = 0; e < 4; e++) {
                    uint32_t mk = f2mk(vals[e]);
                    if ((mk >> 20) >= bstar) {
                        if (pos < 2048u) {
                            uint32_t idx = (uint32_t)(i4 * 4 + e);
                            staging[pos] = ((unsigned long long)mk << 32) |
                                           (unsigned long long)(0xFFFFFFFFu - idx);
                            uint32_t rel = mk - (bstar << 20);
                            uint32_t fb  = rel >> 13;
                            if (fb > 4095u) fb = 4095u;
                            atomicAdd(&hist[fb], 1u);
                        }
                        pos++;
                    }
                }
            }
        }
        __syncthreads();
        if (cnt >= (uint32_t)TOPK && cnt <= 2048u) break;
        use_sample = false;
        target = TOPK;
        __syncthreads();
    }
    if (cnt > 2048u) cnt = 2048u;

    {
        uint32_t v = 0;
        if (tid < 256) {
            uint32_t cs = 0;
#pragma unroll
            for (int b = tid * 16; b < tid * 16 + 16; b++) cs += hist[b];
            v = cs;
#pragma unroll
            for (int o = 1; o < 32; o <<= 1) {
                uint32_t u = __shfl_down_sync(0xFFFFFFFFu, v, o);
                if (lane + o < 32) v += u;
            }
            if (lane == 0) warp_aux[wid] = v;
        }
        __syncthreads();
        if (tid < 8) {
            uint32_t w = warp_aux[tid];
            uint32_t incl2 = w;
#pragma unroll
            for (int o = 1; o < 8; o <<= 1) {
                uint32_t u = __shfl_down_sync(0xFFu, incl2, o);
                if (tid + o < 8) incl2 += u;
            }
            warp_aux[8 + tid] = incl2 - w;
        }
        __syncthreads();
        if (tid < 256) chunksum[tid] = v + warp_aux[8 + wid];
        __syncthreads();
    }
    if (tid < 256) {
        uint32_t acc = (tid < 255) ? chunksum[tid + 1] : 0;
        for (int b = tid * 16 + 15; b >= tid * 16; b--) {
            uint32_t c2 = hist[b];
            hist[b] = acc;
            acc += c2;
        }
    }
    __syncthreads();

    {
        uint32_t lmin = cnt;
#pragma unroll
        for (int s = 0; s < 8; s++) {
            uint32_t b = hist[tid + s * 512];
            if (b >= (uint32_t)TOPK && b < lmin) lmin = b;
        }
        s_redu[tid] = lmin;
        __syncthreads();
        for (int o = 256; o; o >>= 1) {
            if (tid < o) {
                uint32_t a = s_redu[tid], b = s_redu[tid + o];
                s_redu[tid] = (b < a) ? b : a;
            }
            __syncthreads();
        }
    }
    const int end = (int)s_redu[0];
    __syncthreads();

    for (int i = tid; i < (int)cnt; i += 512) {
        unsigned long long k = staging[i];
        uint32_t mk  = (uint32_t)(k >> 32);
        uint32_t rel = mk - (bstar << 20);
        uint32_t fb  = rel >> 13;
        if (fb > 4095u) fb = 4095u;
        if (hist[fb] < (uint32_t)end) {
            uint32_t p = atomicAdd(&hist[fb], 1u);
            fin[p] = k;
        }
    }
    __syncthreads();

    while (true) {
        int moved = 0;
#pragma unroll
        for (int r = 0; r < 2; r++) {
            int i = tid + r * 512;
            int p = 2 * i;
            if (p + 1 < end) {
                unsigned long long a = fin[p], b = fin[p + 1];
                if (a < b) { fin[p] = b; fin[p + 1] = a; moved = 1; }
            }
        }
        __syncthreads();
#pragma unroll
        for (int r = 0; r < 2; r++) {
            int i = tid + r * 512;
            int p = 2 * i + 1;
            if (p + 1 < end) {
                unsigned long long a = fin[p], b = fin[p + 1];
                if (a < b) { fin[p] = b; fin[p + 1] = a; moved = 1; }
            }
        }
        if (!__syncthreads_or(moved)) break;
    }

    const float vmax = mk2f((uint32_t)(fin[0] >> 32));
    unsigned long long p0 = fin[tid];
    unsigned long long p1 = fin[tid + 512];
    float e0 = expf(mk2f((uint32_t)(p0 >> 32)) - vmax);
    float e1 = expf(mk2f((uint32_t)(p1 >> 32)) - vmax);
    s_red[tid] = e0 + e1;
    __syncthreads();
    for (int o = 256; o; o >>= 1) {
        if (tid < o) s_red[tid] += s_red[tid + o];
        __syncthreads();
    }
    const float inv = 1.f / s_red[0];

    const int bud = budget[t];
    const size_t base = (size_t)t * TOPK;
    {
        uint32_t idx0 = 0xFFFFFFFFu - (uint32_t)(p0 & 0xFFFFFFFFull);
        float m0 = (tid < bud) ? 1.f : 0.f;
        out_idx[base + tid] = (float)idx0;
        out_w[base + tid]   = e0 * inv * m0;
        out_m[base + tid]   = m0;
        uint32_t idx1 = 0xFFFFFFFFu - (uint32_t)(p1 & 0xFFFFFFFFull);
        int jj = tid + 512;
        float m1 = (jj < bud) ? 1.f : 0.f;
        out_idx[base + jj] = (float)idx1;
        out_w[base + jj]   = e1 * inv * m1;
        out_m[base + jj]   = m1;
    }
    #undef S_BSTAR
    #undef S_CNT
}

// ---------------- launch: low-priority topk stream, 4-chunk pipeline ---------
extern "C" void kernel_launch(void* const* d_in, const int* in_sizes, int n_in,
                              void* d_out, int out_size)
{
    const float* x   = (const float*)d_in[0];
    const float* w1c = (const float*)d_in[1];
    const float* b1c = (const float*)d_in[2];
    const float* w2c = (const float*)d_in[3];
    const float* b2c = (const float*)d_in[4];
    const float* ws1 = (const float*)d_in[5];
    const float* bs1 = (const float*)d_in[6];
    const float* ws2 = (const float*)d_in[7];
    const float* bs2 = (const float*)d_in[8];

    float* out     = (float*)d_out;
    float* out_idx = out;
    float* out_w   = out + (size_t)NTOK * TOPK;
    float* out_m   = out + 2 * (size_t)NTOK * TOPK;
    float* out_c   = out + 3 * (size_t)NTOK * TOPK;

    float *hs_p, *hc_p, *sc_p;
    int *bud_p;
    cudaGetSymbolAddress((void**)&hs_p,  g_hs);
    cudaGetSymbolAddress((void**)&hc_p,  g_hc);
    cudaGetSymbolAddress((void**)&sc_p,  g_scores);
    cudaGetSymbolAddress((void**)&bud_p, g_budget);

    const int TOPK_SMEM = 53248;   // 52 KB dynamic

    static bool init_done = false;
    static cudaStream_t sB;
    static cudaEvent_t evG[NCHUNK];
    static cudaEvent_t evJoin;
    if (!init_done) {
        cudaFuncSetAttribute(topk_kernel,
                             cudaFuncAttributeMaxDynamicSharedMemorySize, TOPK_SMEM);
        int prLow = 0, prHigh = 0;
        cudaDeviceGetStreamPriorityRange(&prLow, &prHigh);   // prLow = LEAST urgent
        cudaStreamCreateWithPriority(&sB, cudaStreamNonBlocking, prLow);
        for (int i = 0; i < NCHUNK; i++)
            cudaEventCreateWithFlags(&evG[i], cudaEventDisableTiming);
        cudaEventCreateWithFlags(&evJoin, cudaEventDisableTiming);
        init_done = true;
    }

    // stream 0: small GEMMs + complexity
    small_gemms<<<dim3(3, NTOK / 128), 256>>>(x, ws1, bs1, w1c, b1c, hs_p, hc_p);
    complexity_kernel<<<NTOK / 8, 256>>>(hc_p, w2c, b2c, out_c, bud_p);

    // pipelined: GEMM2 chunk c on stream 0 (default prio);
    // topk chunk c on LOW-priority stream B after evG[c] -> fills GEMM bubbles
    for (int c = 0; c < NCHUNK; c++) {
        const size_t trow = (size_t)c * TOKC;
        sgemm2_bias<<<dim3(POOL / 128, TOKC / 128), 256>>>(
            hs_p + trow * HID, ws2, bs2, sc_p + trow * POOL, POOL, HID);
        cudaEventRecord(evG[c], 0);
        cudaStreamWaitEvent(sB, evG[c], 0);
        topk_kernel<<<TOKC, 512, TOPK_SMEM, sB>>>(
            sc_p + trow * POOL, bud_p + trow,
            out_idx + trow * TOPK, out_w + trow * TOPK, out_m + trow * TOPK);
    }
    // join stream B back into stream 0
    cudaEventRecord(evJoin, sB);
    cudaStreamWaitEvent(0, evJoin, 0);
}

// round 14
// speedup vs baseline: 1.0484x; 1.0198x over previous
#include <cuda_runtime.h>
#include <cstdint>
#include <math.h>

#define NTOK 8192
#define DIM  1024
#define HID  256
#define HIDC 128
#define POOL 16384
#define TOPK 1024

// ---------------- scratch (device globals: no allocations allowed) ----------
__device__ float g_hs[NTOK * HID];                              // 8 MB
__device__ float g_hc[NTOK * HIDC];                             // 4 MB
__device__ float g_scores[(size_t)NTOK * POOL];                 // 512 MB
__device__ int   g_budget[NTOK];

// packed fp32x2 FMA (sm_100+): two independent rn-rounded fp32 FMAs per issue.
__device__ __forceinline__ float2 ffma2(float2 a, float2 b, float2 c) {
    unsigned long long A = *(unsigned long long*)&a;
    unsigned long long B = *(unsigned long long*)&b;
    unsigned long long C = *(unsigned long long*)&c;
    unsigned long long D;
    asm("fma.rn.f32x2 %0, %1, %2, %3;" : "=l"(D) : "l"(A), "l"(B), "l"(C));
    return *(float2*)&D;
}

// ---------------- fp32x2 GEMM core (proven R2 version) ----------------------
template<bool RELU>
__device__ __forceinline__ void gemm_body(const float* __restrict__ A,
                                          const float* __restrict__ B,
                                          const float* __restrict__ bias,
                                          float* __restrict__ C,
                                          int N, int K, int bm, int bn,
                                          float Asm[2][8][128], float Bsm[2][8][128])
{
    const int tid = threadIdx.x;
    const int tx  = tid & 15;
    const int ty  = tid >> 4;

    float2 acc[8][4];
#pragma unroll
    for (int i = 0; i < 8; i++)
#pragma unroll
        for (int q = 0; q < 4; q++) acc[i][q] = make_float2(0.f, 0.f);

    const int ar = tid >> 1;
    const int ac = (tid & 1) * 4;
    const int br = tid >> 5;
    const int bc = (tid & 31) * 4;
    const float* Aptr = A + (size_t)(bm + ar) * K + ac;
    const float* Bptr = B + (size_t)br * N + bn + bc;

    const int NT = K >> 3;

    float4 av = *(const float4*)(Aptr);
    float4 bv = *(const float4*)(Bptr);
    Asm[0][ac + 0][ar] = av.x; Asm[0][ac + 1][ar] = av.y;
    Asm[0][ac + 2][ar] = av.z; Asm[0][ac + 3][ar] = av.w;
    *(float4*)&Bsm[0][br][bc] = bv;
    __syncthreads();

    for (int t = 0; t < NT; t++) {
        const int buf = t & 1;
        const bool more = (t + 1) < NT;
        if (more) {
            av = *(const float4*)(Aptr + (t + 1) * 8);
            bv = *(const float4*)(Bptr + (size_t)(t + 1) * 8 * N);
        }

#pragma unroll
        for (int k = 0; k < 8; k++) {
            float4 a0 = *(const float4*)&Asm[buf][k][ty * 8];
            float4 a1 = *(const float4*)&Asm[buf][k][ty * 8 + 4];
            float4 b0 = *(const float4*)&Bsm[buf][k][tx * 4];
            float4 b1 = *(const float4*)&Bsm[buf][k][tx * 4 + 64];
            float2 bp[4];
            bp[0] = make_float2(b0.x, b0.y); bp[1] = make_float2(b0.z, b0.w);
            bp[2] = make_float2(b1.x, b1.y); bp[3] = make_float2(b1.z, b1.w);
            float a[8] = {a0.x, a0.y, a0.z, a0.w, a1.x, a1.y, a1.z, a1.w};
#pragma unroll
            for (int i = 0; i < 8; i++) {
                float2 ad = make_float2(a[i], a[i]);
#pragma unroll
                for (int q = 0; q < 4; q++)
                    acc[i][q] = ffma2(ad, bp[q], acc[i][q]);
            }
        }

        if (more) {
            const int nb = buf ^ 1;
            Asm[nb][ac + 0][ar] = av.x; Asm[nb][ac + 1][ar] = av.y;
            Asm[nb][ac + 2][ar] = av.z; Asm[nb][ac + 3][ar] = av.w;
            *(float4*)&Bsm[nb][br][bc] = bv;
        }
        __syncthreads();
    }

#pragma unroll
    for (int i = 0; i < 8; i++) {
        const int row = bm + ty * 8 + i;
#pragma unroll
        for (int g = 0; g < 2; g++) {
            const int col = bn + tx * 4 + g * 64;
            float4 v;
            v.x = acc[i][g * 2 + 0].x + bias[col + 0];
            v.y = acc[i][g * 2 + 0].y + bias[col + 1];
            v.z = acc[i][g * 2 + 1].x + bias[col + 2];
            v.w = acc[i][g * 2 + 1].y + bias[col + 3];
            if (RELU) {
                v.x = fmaxf(v.x, 0.f); v.y = fmaxf(v.y, 0.f);
                v.z = fmaxf(v.z, 0.f); v.w = fmaxf(v.w, 0.f);
            }
            *(float4*)(C + (size_t)row * N + col) = v;
        }
    }
}

__global__ void __launch_bounds__(256, 2)
sgemm2_bias(const float* __restrict__ A, const float* __restrict__ B,
            const float* __restrict__ bias, float* __restrict__ C,
            int N, int K)
{
    __shared__ float As[2][8][128];
    __shared__ float Bs[2][8][128];
    gemm_body<false>(A, B, bias, C, N, K, blockIdx.y * 128, blockIdx.x * 128, As, Bs);
}

__global__ void __launch_bounds__(256, 2)
small_gemms(const float* __restrict__ x,
            const float* __restrict__ ws1, const float* __restrict__ bs1,
            const float* __restrict__ w1c, const float* __restrict__ b1c,
            float* __restrict__ hs, float* __restrict__ hc)
{
    __shared__ float As[2][8][128];
    __shared__ float Bs[2][8][128];
    const int bx = blockIdx.x;
    if (bx < 2)
        gemm_body<true>(x, ws1, bs1, hs, HID,  DIM, blockIdx.y * 128, bx * 128, As, Bs);
    else
        gemm_body<true>(x, w1c, b1c, hc, HIDC, DIM, blockIdx.y * 128, 0, As, Bs);
}

// ---------------- complexity -> sigmoid -> budget ---------------------------
__global__ void complexity_kernel(const float* __restrict__ hc,
                                  const float* __restrict__ w2c,
                                  const float* __restrict__ b2c,
                                  float* __restrict__ out_c,
                                  int* __restrict__ budget)
{
    int warp = (blockIdx.x * blockDim.x + threadIdx.x) >> 5;
    int lane = threadIdx.x & 31;
    if (warp >= NTOK) return;
    const float* h = hc + (size_t)warp * HIDC;
    float s = 0.f;
#pragma unroll
    for (int i = lane; i < HIDC; i += 32) s += h[i] * w2c[i];
#pragma unroll
    for (int o = 16; o; o >>= 1) s += __shfl_xor_sync(0xFFFFFFFFu, s, o);
    if (lane == 0) {
        float z = s + b2c[0];
        float c = 1.f / (1.f + expf(-z));
        out_c[warp] = c;
        float raw = 100.f + 924.f * (c * c);
        raw = fminf(fmaxf(raw, 100.f), 1024.f);
        budget[warp] = (int)rintf(raw);
    }
}

// ---------------- top-k helpers ---------------------------------------------
__device__ __forceinline__ uint32_t f2mk(float f) {
    uint32_t u = __float_as_uint(f);
    return (u & 0x80000000u) ? ~u : (u | 0x80000000u);
}
__device__ __forceinline__ float mk2f(uint32_t mk) {
    uint32_t u = (mk & 0x80000000u) ? (mk ^ 0x80000000u) : ~mk;
    return __uint_as_float(u);
}

// ---------------- fused top-k: threshold select + direct counting scatter ---
// smem (dynamic ~37 KB): fin[2048] u64 | hist[4096] u32 | chunksum[256] u32 |
//   warp_aux[32] u32 | s_red[512] f32 | scal[4] u32
__global__ void __launch_bounds__(512, 2)
topk_kernel(const float* __restrict__ scores, const int* __restrict__ budget,
            float* __restrict__ out_idx, float* __restrict__ out_w,
            float* __restrict__ out_m)
{
    extern __shared__ char smem_raw[];
    unsigned long long* fin = (unsigned long long*)smem_raw;
    uint32_t* hist     = (uint32_t*)(fin + 2048);
    uint32_t* chunksum = hist + 4096;
    uint32_t* warp_aux = chunksum + 256;
    float*    s_red    = (float*)(warp_aux + 32);
    uint32_t* s_redu   = (uint32_t*)s_red;
    uint32_t* scal     = (uint32_t*)(s_red + 512);
    #define S_BSTAR scal[0]

    const int t    = blockIdx.x;
    const int tid  = threadIdx.x;
    const int lane = tid & 31;
    const int wid  = tid >> 5;
    const float4* row4 = (const float4*)(scores + (size_t)t * POOL);

    uint32_t cnt = 0, bstar = 0;
    bool     use_sample = true;
    uint32_t target = 192;           // 2048-sample -> expected survivors ~1536

    for (int attempt = 0; attempt < 2; attempt++) {
        for (int i = tid; i < 4096; i += 512) hist[i] = 0;
        __syncthreads();

        // coarse (12-bit) histogram: contiguous 2048-sample or exact full row
        if (use_sample) {
            float4 v = row4[tid];
            atomicAdd(&hist[f2mk(v.x) >> 20], 1u);
            atomicAdd(&hist[f2mk(v.y) >> 20], 1u);
            atomicAdd(&hist[f2mk(v.z) >> 20], 1u);
            atomicAdd(&hist[f2mk(v.w) >> 20], 1u);
        } else {
#pragma unroll
            for (int s = 0; s < 8; s++) {
                float4 v = row4[tid + s * 512];
                atomicAdd(&hist[f2mk(v.x) >> 20], 1u);
                atomicAdd(&hist[f2mk(v.y) >> 20], 1u);
                atomicAdd(&hist[f2mk(v.z) >> 20], 1u);
                atomicAdd(&hist[f2mk(v.w) >> 20], 1u);
            }
        }
        __syncthreads();

        // suffix scan over 256 chunk sums (warp shuffles)
        {
            uint32_t v = 0;
            if (tid < 256) {
                uint32_t cs = 0;
#pragma unroll
                for (int b = tid * 16; b < tid * 16 + 16; b++) cs += hist[b];
                v = cs;
#pragma unroll
                for (int o = 1; o < 32; o <<= 1) {
                    uint32_t u = __shfl_down_sync(0xFFFFFFFFu, v, o);
                    if (lane + o < 32) v += u;
                }
                if (lane == 0) warp_aux[wid] = v;
            }
            __syncthreads();
            if (tid < 8) {
                uint32_t w = warp_aux[tid];
                uint32_t incl = w;
#pragma unroll
                for (int o = 1; o < 8; o <<= 1) {
                    uint32_t u = __shfl_down_sync(0xFFu, incl, o);
                    if (tid + o < 8) incl += u;
                }
                warp_aux[8 + tid] = incl - w;
            }
            __syncthreads();
            if (tid < 256) chunksum[tid] = v + warp_aux[8 + wid];
            __syncthreads();
        }

        // crossing chunk -> threshold bin bstar
        if (tid < 256) {
            uint32_t Sc = chunksum[tid];
            uint32_t Sn = (tid < 255) ? chunksum[tid + 1] : 0;
            if (Sc >= target && Sn < target) {
                uint32_t cum = Sn;
                int b;
                for (b = tid * 16 + 15; b > tid * 16; b--) {
                    cum += hist[b];
                    if (cum >= target) break;
                }
                S_BSTAR = (uint32_t)b;
            }
        }
        __syncthreads();
        bstar = S_BSTAR;

        // clear hist for reuse as FINE histogram
        for (int i = tid; i < 4096; i += 512) hist[i] = 0;
        __syncthreads();

        // pass A: count survivors + build fine histogram (spread atomics)
        uint32_t c = 0;
#pragma unroll
        for (int h = 0; h < 2; h++) {
            float4 vv[4];
#pragma unroll
            for (int s = 0; s < 4; s++) vv[s] = row4[tid + (h * 4 + s) * 512];
#pragma unroll
            for (int s = 0; s < 4; s++) {
                float vals[4] = {vv[s].x, vv[s].y, vv[s].z, vv[s].w};
#pragma unroll
                for (int e = 0; e < 4; e++) {
                    uint32_t mk = f2mk(vals[e]);
                    if ((mk >> 20) >= bstar) {
                        c++;
                        uint32_t rel = mk - (bstar << 20);
                        uint32_t fb  = rel >> 13;
                        if (fb > 4095u) fb = 4095u;
                        atomicAdd(&hist[fb], 1u);
                    }
                }
            }
        }
        // block reduce of counts -> cnt
        s_redu[tid] = c;
        __syncthreads();
        for (int o = 256; o; o >>= 1) {
            if (tid < o) s_redu[tid] += s_redu[tid + o];
            __syncthreads();
        }
        cnt = s_redu[0];
        __syncthreads();
        if (cnt >= (uint32_t)TOPK && cnt <= 2048u) break;
        use_sample = false;
        target = TOPK;
        __syncthreads();
    }
    if (cnt > 2048u) cnt = 2048u;

    // suffix scan fine hist -> per-bin scatter bases (desc order)
    {
        uint32_t v = 0;
        if (tid < 256) {
            uint32_t cs = 0;
#pragma unroll
            for (int b = tid * 16; b < tid * 16 + 16; b++) cs += hist[b];
            v = cs;
#pragma unroll
            for (int o = 1; o < 32; o <<= 1) {
                uint32_t u = __shfl_down_sync(0xFFFFFFFFu, v, o);
                if (lane + o < 32) v += u;
            }
            if (lane == 0) warp_aux[wid] = v;
        }
        __syncthreads();
        if (tid < 8) {
            uint32_t w = warp_aux[tid];
            uint32_t incl2 = w;
#pragma unroll
            for (int o = 1; o < 8; o <<= 1) {
                uint32_t u = __shfl_down_sync(0xFFu, incl2, o);
                if (tid + o < 8) incl2 += u;
            }
            warp_aux[8 + tid] = incl2 - w;
        }
        __syncthreads();
        if (tid < 256) chunksum[tid] = v + warp_aux[8 + wid];
        __syncthreads();
    }
    if (tid < 256) {
        uint32_t acc = (tid < 255) ? chunksum[tid + 1] : 0;
        for (int b = tid * 16 + 15; b >= tid * 16; b--) {
            uint32_t c2 = hist[b];
            hist[b] = acc;          // base for bin b = count in bins > b
            acc += c2;
        }
    }
    __syncthreads();

    // end = min{ base[fb] : base >= 1024 } (prefix containing the top-1024)
    {
        uint32_t lmin = cnt;
#pragma unroll
        for (int s = 0; s < 8; s++) {
            uint32_t b = hist[tid + s * 512];
            if (b >= (uint32_t)TOPK && b < lmin) lmin = b;
        }
        s_redu[tid] = lmin;
        __syncthreads();
        for (int o = 256; o; o >>= 1) {
            if (tid < o) {
                uint32_t a = s_redu[tid], b = s_redu[tid + o];
                s_redu[tid] = (b < a) ? b : a;
            }
            __syncthreads();
        }
    }
    int end = (int)s_redu[0];
    if (end > 2048) end = 2048;
    __syncthreads();

    // pass B: re-read row, scatter survivors DIRECTLY into fin
    // (prefix bins land exactly in [base, base+size) subset of [0, end);
    //  bins with base >= end are skipped entirely -> deterministic set)
#pragma unroll
    for (int h = 0; h < 2; h++) {
        float4 vv[4];
#pragma unroll
        for (int s = 0; s < 4; s++) vv[s] = row4[tid + (h * 4 + s) * 512];
#pragma unroll
        for (int s = 0; s < 4; s++) {
            const int i4 = tid + (h * 4 + s) * 512;
            float vals[4] = {vv[s].x, vv[s].y, vv[s].z, vv[s].w};
#pragma unroll
            for (int e = 0; e < 4; e++) {
                uint32_t mk = f2mk(vals[e]);
                if ((mk >> 20) >= bstar) {
                    uint32_t rel = mk - (bstar << 20);
                    uint32_t fb  = rel >> 13;
                    if (fb > 4095u) fb = 4095u;
                    if (hist[fb] < (uint32_t)end) {
                        uint32_t p = atomicAdd(&hist[fb], 1u);
                        uint32_t idx = (uint32_t)(i4 * 4 + e);
                        fin[p] = ((unsigned long long)mk << 32) |
                                 (unsigned long long)(0xFFFFFFFFu - idx);
                    }
                }
            }
        }
    }
    __syncthreads();

    // odd-even transposition over [0, end) until sorted (intra-bin fixup)
    while (true) {
        int moved = 0;
#pragma unroll
        for (int r = 0; r < 2; r++) {
            int i = tid + r * 512;
            int p = 2 * i;
            if (p + 1 < end) {
                unsigned long long a = fin[p], b = fin[p + 1];
                if (a < b) { fin[p] = b; fin[p + 1] = a; moved = 1; }
            }
        }
        __syncthreads();
#pragma unroll
        for (int r = 0; r < 2; r++) {
            int i = tid + r * 512;
            int p = 2 * i + 1;
            if (p + 1 < end) {
                unsigned long long a = fin[p], b = fin[p + 1];
                if (a < b) { fin[p] = b; fin[p + 1] = a; moved = 1; }
            }
        }
        if (!__syncthreads_or(moved)) break;
    }

    // softmax over sorted top-1024 + budget mask (tree reduce: bit-stable)
    const float vmax = mk2f((uint32_t)(fin[0] >> 32));
    unsigned long long p0 = fin[tid];
    unsigned long long p1 = fin[tid + 512];
    float e0 = expf(mk2f((uint32_t)(p0 >> 32)) - vmax);
    float e1 = expf(mk2f((uint32_t)(p1 >> 32)) - vmax);
    s_red[tid] = e0 + e1;
    __syncthreads();
    for (int o = 256; o; o >>= 1) {
        if (tid < o) s_red[tid] += s_red[tid + o];
        __syncthreads();
    }
    const float inv = 1.f / s_red[0];

    const int bud = budget[t];
    const size_t base = (size_t)t * TOPK;
    {
        uint32_t idx0 = 0xFFFFFFFFu - (uint32_t)(p0 & 0xFFFFFFFFull);
        float m0 = (tid < bud) ? 1.f : 0.f;
        out_idx[base + tid] = (float)idx0;
        out_w[base + tid]   = e0 * inv * m0;
        out_m[base + tid]   = m0;
        uint32_t idx1 = 0xFFFFFFFFu - (uint32_t)(p1 & 0xFFFFFFFFull);
        int jj = tid + 512;
        float m1 = (jj < bud) ? 1.f : 0.f;
        out_idx[base + jj] = (float)idx1;
        out_w[base + jj]   = e1 * inv * m1;
        out_m[base + jj]   = m1;
    }
    #undef S_BSTAR
}

// ---------------- launch: serial (R10 structure) ------------------------------
extern "C" void kernel_launch(void* const* d_in, const int* in_sizes, int n_in,
                              void* d_out, int out_size)
{
    const float* x   = (const float*)d_in[0];
    const float* w1c = (const float*)d_in[1];
    const float* b1c = (const float*)d_in[2];
    const float* w2c = (const float*)d_in[3];
    const float* b2c = (const float*)d_in[4];
    const float* ws1 = (const float*)d_in[5];
    const float* bs1 = (const float*)d_in[6];
    const float* ws2 = (const float*)d_in[7];
    const float* bs2 = (const float*)d_in[8];

    float* out     = (float*)d_out;
    float* out_idx = out;
    float* out_w   = out + (size_t)NTOK * TOPK;
    float* out_m   = out + 2 * (size_t)NTOK * TOPK;
    float* out_c   = out + 3 * (size_t)NTOK * TOPK;

    float *hs_p, *hc_p, *sc_p;
    int *bud_p;
    cudaGetSymbolAddress((void**)&hs_p,  g_hs);
    cudaGetSymbolAddress((void**)&hc_p,  g_hc);
    cudaGetSymbolAddress((void**)&sc_p,  g_scores);
    cudaGetSymbolAddress((void**)&bud_p, g_budget);

    const int TOPK_SMEM = 38912;   // 38 KB dynamic
    static bool attr_set = false;
    if (!attr_set) {
        cudaFuncSetAttribute(topk_kernel,
                             cudaFuncAttributeMaxDynamicSharedMemorySize, TOPK_SMEM);
        attr_set = true;
    }

    small_gemms<<<dim3(3, NTOK / 128), 256>>>(x, ws1, bs1, w1c, b1c, hs_p, hc_p);
    complexity_kernel<<<NTOK / 8, 256>>>(hc_p, w2c, b2c, out_c, bud_p);
    sgemm2_bias<<<dim3(POOL / 128, NTOK / 128), 256>>>(hs_p, ws2, bs2, sc_p, POOL, HID);
    topk_kernel<<<NTOK, 512, TOPK_SMEM>>>(sc_p, bud_p, out_idx, out_w, out_m);
}

// round 15
// speedup vs baseline: 1.0543x; 1.0056x over previous
#include <cuda_runtime.h>
#include <cstdint>
#include <math.h>

#define NTOK 8192
#define DIM  1024
#define HID  256
#define HIDC 128
#define POOL 16384
#define TOPK 1024

// ---------------- scratch (device globals: no allocations allowed) ----------
__device__ float g_hs[NTOK * HID];                              // 8 MB
__device__ float g_hc[NTOK * HIDC];                             // 4 MB
__device__ float g_scores[(size_t)NTOK * POOL];                 // 512 MB
__device__ int   g_budget[NTOK];

// packed fp32x2 FMA (sm_100+): two independent rn-rounded fp32 FMAs per issue.
__device__ __forceinline__ float2 ffma2(float2 a, float2 b, float2 c) {
    unsigned long long A = *(unsigned long long*)&a;
    unsigned long long B = *(unsigned long long*)&b;
    unsigned long long C = *(unsigned long long*)&c;
    unsigned long long D;
    asm("fma.rn.f32x2 %0, %1, %2, %3;" : "=l"(D) : "l"(A), "l"(B), "l"(C));
    return *(float2*)&D;
}

// ---------------- fp32x2 GEMM core (proven R2 version) ----------------------
template<bool RELU>
__device__ __forceinline__ void gemm_body(const float* __restrict__ A,
                                          const float* __restrict__ B,
                                          const float* __restrict__ bias,
                                          float* __restrict__ C,
                                          int N, int K, int bm, int bn,
                                          float Asm[2][8][128], float Bsm[2][8][128])
{
    const int tid = threadIdx.x;
    const int tx  = tid & 15;
    const int ty  = tid >> 4;

    float2 acc[8][4];
#pragma unroll
    for (int i = 0; i < 8; i++)
#pragma unroll
        for (int q = 0; q < 4; q++) acc[i][q] = make_float2(0.f, 0.f);

    const int ar = tid >> 1;
    const int ac = (tid & 1) * 4;
    const int br = tid >> 5;
    const int bc = (tid & 31) * 4;
    const float* Aptr = A + (size_t)(bm + ar) * K + ac;
    const float* Bptr = B + (size_t)br * N + bn + bc;

    const int NT = K >> 3;

    float4 av = *(const float4*)(Aptr);
    float4 bv = *(const float4*)(Bptr);
    Asm[0][ac + 0][ar] = av.x; Asm[0][ac + 1][ar] = av.y;
    Asm[0][ac + 2][ar] = av.z; Asm[0][ac + 3][ar] = av.w;
    *(float4*)&Bsm[0][br][bc] = bv;
    __syncthreads();

    for (int t = 0; t < NT; t++) {
        const int buf = t & 1;
        const bool more = (t + 1) < NT;
        if (more) {
            av = *(const float4*)(Aptr + (t + 1) * 8);
            bv = *(const float4*)(Bptr + (size_t)(t + 1) * 8 * N);
        }

#pragma unroll
        for (int k = 0; k < 8; k++) {
            float4 a0 = *(const float4*)&Asm[buf][k][ty * 8];
            float4 a1 = *(const float4*)&Asm[buf][k][ty * 8 + 4];
            float4 b0 = *(const float4*)&Bsm[buf][k][tx * 4];
            float4 b1 = *(const float4*)&Bsm[buf][k][tx * 4 + 64];
            float2 bp[4];
            bp[0] = make_float2(b0.x, b0.y); bp[1] = make_float2(b0.z, b0.w);
            bp[2] = make_float2(b1.x, b1.y); bp[3] = make_float2(b1.z, b1.w);
            float a[8] = {a0.x, a0.y, a0.z, a0.w, a1.x, a1.y, a1.z, a1.w};
#pragma unroll
            for (int i = 0; i < 8; i++) {
                float2 ad = make_float2(a[i], a[i]);
#pragma unroll
                for (int q = 0; q < 4; q++)
                    acc[i][q] = ffma2(ad, bp[q], acc[i][q]);
            }
        }

        if (more) {
            const int nb = buf ^ 1;
            Asm[nb][ac + 0][ar] = av.x; Asm[nb][ac + 1][ar] = av.y;
            Asm[nb][ac + 2][ar] = av.z; Asm[nb][ac + 3][ar] = av.w;
            *(float4*)&Bsm[nb][br][bc] = bv;
        }
        __syncthreads();
    }

#pragma unroll
    for (int i = 0; i < 8; i++) {
        const int row = bm + ty * 8 + i;
#pragma unroll
        for (int g = 0; g < 2; g++) {
            const int col = bn + tx * 4 + g * 64;
            float4 v;
            v.x = acc[i][g * 2 + 0].x + bias[col + 0];
            v.y = acc[i][g * 2 + 0].y + bias[col + 1];
            v.z = acc[i][g * 2 + 1].x + bias[col + 2];
            v.w = acc[i][g * 2 + 1].y + bias[col + 3];
            if (RELU) {
                v.x = fmaxf(v.x, 0.f); v.y = fmaxf(v.y, 0.f);
                v.z = fmaxf(v.z, 0.f); v.w = fmaxf(v.w, 0.f);
            }
            *(float4*)(C + (size_t)row * N + col) = v;
        }
    }
}

__global__ void __launch_bounds__(256, 2)
sgemm2_bias(const float* __restrict__ A, const float* __restrict__ B,
            const float* __restrict__ bias, float* __restrict__ C,
            int N, int K)
{
    __shared__ float As[2][8][128];
    __shared__ float Bs[2][8][128];
    gemm_body<false>(A, B, bias, C, N, K, blockIdx.y * 128, blockIdx.x * 128, As, Bs);
}

__global__ void __launch_bounds__(256, 2)
small_gemms(const float* __restrict__ x,
            const float* __restrict__ ws1, const float* __restrict__ bs1,
            const float* __restrict__ w1c, const float* __restrict__ b1c,
            float* __restrict__ hs, float* __restrict__ hc)
{
    __shared__ float As[2][8][128];
    __shared__ float Bs[2][8][128];
    const int bx = blockIdx.x;
    if (bx < 2)
        gemm_body<true>(x, ws1, bs1, hs, HID,  DIM, blockIdx.y * 128, bx * 128, As, Bs);
    else
        gemm_body<true>(x, w1c, b1c, hc, HIDC, DIM, blockIdx.y * 128, 0, As, Bs);
}

// ---------------- complexity -> sigmoid -> budget ---------------------------
__global__ void complexity_kernel(const float* __restrict__ hc,
                                  const float* __restrict__ w2c,
                                  const float* __restrict__ b2c,
                                  float* __restrict__ out_c,
                                  int* __restrict__ budget)
{
    int warp = (blockIdx.x * blockDim.x + threadIdx.x) >> 5;
    int lane = threadIdx.x & 31;
    if (warp >= NTOK) return;
    const float* h = hc + (size_t)warp * HIDC;
    float s = 0.f;
#pragma unroll
    for (int i = lane; i < HIDC; i += 32) s += h[i] * w2c[i];
#pragma unroll
    for (int o = 16; o; o >>= 1) s += __shfl_xor_sync(0xFFFFFFFFu, s, o);
    if (lane == 0) {
        float z = s + b2c[0];
        float c = 1.f / (1.f + expf(-z));
        out_c[warp] = c;
        float raw = 100.f + 924.f * (c * c);
        raw = fminf(fmaxf(raw, 100.f), 1024.f);
        budget[warp] = (int)rintf(raw);
    }
}

// ---------------- top-k helpers ---------------------------------------------
__device__ __forceinline__ uint32_t f2mk(float f) {
    uint32_t u = __float_as_uint(f);
    return (u & 0x80000000u) ? ~u : (u | 0x80000000u);
}
__device__ __forceinline__ float mk2f(uint32_t mk) {
    uint32_t u = (mk & 0x80000000u) ? (mk ^ 0x80000000u) : ~mk;
    return __uint_as_float(u);
}

// ---------------- fused top-k: float-domain threshold + counting scatter ----
// smem (dynamic ~37 KB): fin[2048] u64 | hist[4096] u32 | chunksum[256] u32 |
//   warp_aux[32] u32 | s_red[512] f32 | scal[4] u32
__global__ void __launch_bounds__(512, 2)
topk_kernel(const float* __restrict__ scores, const int* __restrict__ budget,
            float* __restrict__ out_idx, float* __restrict__ out_w,
            float* __restrict__ out_m)
{
    extern __shared__ char smem_raw[];
    unsigned long long* fin = (unsigned long long*)smem_raw;
    uint32_t* hist     = (uint32_t*)(fin + 2048);
    uint32_t* chunksum = hist + 4096;
    uint32_t* warp_aux = chunksum + 256;
    float*    s_red    = (float*)(warp_aux + 32);
    uint32_t* scal     = (uint32_t*)(s_red + 512);
    #define S_BSTAR scal[0]
    #define S_CNT   scal[1]
    #define S_END   scal[2]

    const int t    = blockIdx.x;
    const int tid  = threadIdx.x;
    const int lane = tid & 31;
    const int wid  = tid >> 5;
    const float4* row4 = (const float4*)(scores + (size_t)t * POOL);

    uint32_t cnt = 0, bstar = 0;
    bool     use_sample = true;
    uint32_t target = 192;           // 2048-sample -> expected survivors ~1536

    for (int attempt = 0; attempt < 2; attempt++) {
        for (int i = tid; i < 4096; i += 512) hist[i] = 0;
        if (tid == 0) S_CNT = 0;
        __syncthreads();

        // coarse (12-bit) histogram: contiguous 2048-sample or exact full row
        if (use_sample) {
            float4 v = row4[tid];
            atomicAdd(&hist[f2mk(v.x) >> 20], 1u);
            atomicAdd(&hist[f2mk(v.y) >> 20], 1u);
            atomicAdd(&hist[f2mk(v.z) >> 20], 1u);
            atomicAdd(&hist[f2mk(v.w) >> 20], 1u);
        } else {
#pragma unroll
            for (int s = 0; s < 8; s++) {
                float4 v = row4[tid + s * 512];
                atomicAdd(&hist[f2mk(v.x) >> 20], 1u);
                atomicAdd(&hist[f2mk(v.y) >> 20], 1u);
                atomicAdd(&hist[f2mk(v.z) >> 20], 1u);
                atomicAdd(&hist[f2mk(v.w) >> 20], 1u);
            }
        }
        __syncthreads();

        // suffix scan over 256 chunk sums (warp shuffles)
        {
            uint32_t v = 0;
            if (tid < 256) {
                uint32_t cs = 0;
#pragma unroll
                for (int b = tid * 16; b < tid * 16 + 16; b++) cs += hist[b];
                v = cs;
#pragma unroll
                for (int o = 1; o < 32; o <<= 1) {
                    uint32_t u = __shfl_down_sync(0xFFFFFFFFu, v, o);
                    if (lane + o < 32) v += u;
                }
                if (lane == 0) warp_aux[wid] = v;
            }
            __syncthreads();
            if (tid < 8) {
                uint32_t w = warp_aux[tid];
                uint32_t incl = w;
#pragma unroll
                for (int o = 1; o < 8; o <<= 1) {
                    uint32_t u = __shfl_down_sync(0xFFu, incl, o);
                    if (tid + o < 8) incl += u;
                }
                warp_aux[8 + tid] = incl - w;
            }
            __syncthreads();
            if (tid < 256) chunksum[tid] = v + warp_aux[8 + wid];
            __syncthreads();
        }

        // crossing chunk -> threshold bin bstar
        if (tid < 256) {
            uint32_t Sc = chunksum[tid];
            uint32_t Sn = (tid < 255) ? chunksum[tid + 1] : 0;
            if (Sc >= target && Sn < target) {
                uint32_t cum = Sn;
                int b;
                for (b = tid * 16 + 15; b > tid * 16; b--) {
                    cum += hist[b];
                    if (cum >= target) break;
                }
                S_BSTAR = (uint32_t)b;
            }
        }
        __syncthreads();
        bstar = S_BSTAR;

        // float-domain threshold: score >= thrF  <=>  f2mk(score) >= bstar<<20.
        // Valid whenever the threshold is a positive float (bstar > 2049 keeps
        // us clear of the -0/+0 compare ambiguity); integer fallback otherwise.
        const uint32_t thrkey = bstar << 20;
        const float    thrF   = mk2f(thrkey);
        const bool     fok    = (bstar > 2049u);

        // clear hist for reuse as FINE histogram
        for (int i = tid; i < 4096; i += 512) hist[i] = 0;
        __syncthreads();

        // pass A: count survivors (1 FCMP/elem) + fine histogram (survivors only)
        uint32_t c = 0;
#pragma unroll
        for (int h = 0; h < 2; h++) {
            float4 vv[4];
#pragma unroll
            for (int s = 0; s < 4; s++) vv[s] = row4[tid + (h * 4 + s) * 512];
#pragma unroll
            for (int s = 0; s < 4; s++) {
                float vals[4] = {vv[s].x, vv[s].y, vv[s].z, vv[s].w};
#pragma unroll
                for (int e = 0; e < 4; e++) {
                    bool pred = fok ? (vals[e] >= thrF)
                                    : (f2mk(vals[e]) >= thrkey);
                    if (pred) {
                        c++;
                        uint32_t rel = f2mk(vals[e]) - thrkey;
                        uint32_t fb  = rel >> 13;
                        if (fb > 4095u) fb = 4095u;
                        atomicAdd(&hist[fb], 1u);
                    }
                }
            }
        }
        // warp reduce + single atomic -> cnt
#pragma unroll
        for (int o = 16; o; o >>= 1) c += __shfl_xor_sync(0xFFFFFFFFu, c, o);
        if (lane == 0) atomicAdd(&S_CNT, c);
        __syncthreads();
        cnt = S_CNT;
        if (cnt >= (uint32_t)TOPK && cnt <= 2048u) break;
        use_sample = false;
        target = TOPK;
        __syncthreads();
    }
    if (cnt > 2048u) cnt = 2048u;
    const uint32_t thrkey = bstar << 20;
    const float    thrF   = mk2f(thrkey);
    const bool     fok    = (bstar > 2049u);

    // suffix scan fine hist -> per-bin scatter bases (desc order)
    {
        uint32_t v = 0;
        if (tid < 256) {
            uint32_t cs = 0;
#pragma unroll
            for (int b = tid * 16; b < tid * 16 + 16; b++) cs += hist[b];
            v = cs;
#pragma unroll
            for (int o = 1; o < 32; o <<= 1) {
                uint32_t u = __shfl_down_sync(0xFFFFFFFFu, v, o);
                if (lane + o < 32) v += u;
            }
            if (lane == 0) warp_aux[wid] = v;
        }
        __syncthreads();
        if (tid < 8) {
            uint32_t w = warp_aux[tid];
            uint32_t incl2 = w;
#pragma unroll
            for (int o = 1; o < 8; o <<= 1) {
                uint32_t u = __shfl_down_sync(0xFFu, incl2, o);
                if (tid + o < 8) incl2 += u;
            }
            warp_aux[8 + tid] = incl2 - w;
        }
        __syncthreads();
        if (tid < 256) chunksum[tid] = v + warp_aux[8 + wid];
        if (tid == 0) S_END = cnt;
        __syncthreads();
    }
    if (tid < 256) {
        uint32_t acc = (tid < 255) ? chunksum[tid + 1] : 0;
        for (int b = tid * 16 + 15; b >= tid * 16; b--) {
            uint32_t c2 = hist[b];
            hist[b] = acc;          // base for bin b = count in bins > b
            acc += c2;
        }
    }
    __syncthreads();

    // end = min{ base[fb] : base >= 1024 }  (warp min + one atomicMin)
    {
        uint32_t lmin = cnt;
#pragma unroll
        for (int s = 0; s < 8; s++) {
            uint32_t b = hist[tid + s * 512];
            if (b >= (uint32_t)TOPK && b < lmin) lmin = b;
        }
#pragma unroll
        for (int o = 16; o; o >>= 1) {
            uint32_t u = __shfl_xor_sync(0xFFFFFFFFu, lmin, o);
            if (u < lmin) lmin = u;
        }
        if (lane == 0) atomicMin((int*)&S_END, (int)lmin);
        __syncthreads();
    }
    int end = (int)S_END;
    if (end > 2048) end = 2048;
    __syncthreads();

    // pass B: re-read row (L1-hot), scatter survivors directly into fin
#pragma unroll
    for (int h = 0; h < 2; h++) {
        float4 vv[4];
#pragma unroll
        for (int s = 0; s < 4; s++) vv[s] = row4[tid + (h * 4 + s) * 512];
#pragma unroll
        for (int s = 0; s < 4; s++) {
            const int i4 = tid + (h * 4 + s) * 512;
            float vals[4] = {vv[s].x, vv[s].y, vv[s].z, vv[s].w};
#pragma unroll
            for (int e = 0; e < 4; e++) {
                bool pred = fok ? (vals[e] >= thrF)
                                : (f2mk(vals[e]) >= thrkey);
                if (pred) {
                    uint32_t mk  = f2mk(vals[e]);
                    uint32_t rel = mk - thrkey;
                    uint32_t fb  = rel >> 13;
                    if (fb > 4095u) fb = 4095u;
                    if (hist[fb] < (uint32_t)end) {
                        uint32_t p = atomicAdd(&hist[fb], 1u);
                        uint32_t idx = (uint32_t)(i4 * 4 + e);
                        fin[p] = ((unsigned long long)mk << 32) |
                                 (unsigned long long)(0xFFFFFFFFu - idx);
                    }
                }
            }
        }
    }
    __syncthreads();

    // odd-even transposition over [0, end) until sorted (intra-bin fixup)
    while (true) {
        int moved = 0;
#pragma unroll
        for (int r = 0; r < 2; r++) {
            int i = tid + r * 512;
            int p = 2 * i;
            if (p + 1 < end) {
                unsigned long long a = fin[p], b = fin[p + 1];
                if (a < b) { fin[p] = b; fin[p + 1] = a; moved = 1; }
            }
        }
        __syncthreads();
#pragma unroll
        for (int r = 0; r < 2; r++) {
            int i = tid + r * 512;
            int p = 2 * i + 1;
            if (p + 1 < end) {
                unsigned long long a = fin[p], b = fin[p + 1];
                if (a < b) { fin[p] = b; fin[p + 1] = a; moved = 1; }
            }
        }
        if (!__syncthreads_or(moved)) break;
    }

    // softmax over sorted top-1024 + budget mask (tree reduce: bit-stable)
    const float vmax = mk2f((uint32_t)(fin[0] >> 32));
    unsigned long long p0 = fin[tid];
    unsigned long long p1 = fin[tid + 512];
    float e0 = expf(mk2f((uint32_t)(p0 >> 32)) - vmax);
    float e1 = expf(mk2f((uint32_t)(p1 >> 32)) - vmax);
    s_red[tid] = e0 + e1;
    __syncthreads();
    for (int o = 256; o; o >>= 1) {
        if (tid < o) s_red[tid] += s_red[tid + o];
        __syncthreads();
    }
    const float inv = 1.f / s_red[0];

    const int bud = budget[t];
    const size_t base = (size_t)t * TOPK;
    {
        uint32_t idx0 = 0xFFFFFFFFu - (uint32_t)(p0 & 0xFFFFFFFFull);
        float m0 = (tid < bud) ? 1.f : 0.f;
        out_idx[base + tid] = (float)idx0;
        out_w[base + tid]   = e0 * inv * m0;
        out_m[base + tid]   = m0;
        uint32_t idx1 = 0xFFFFFFFFu - (uint32_t)(p1 & 0xFFFFFFFFull);
        int jj = tid + 512;
        float m1 = (jj < bud) ? 1.f : 0.f;
        out_idx[base + jj] = (float)idx1;
        out_w[base + jj]   = e1 * inv * m1;
        out_m[base + jj]   = m1;
    }
    #undef S_BSTAR
    #undef S_CNT
    #undef S_END
}

// ---------------- launch: serial (R10 structure) ------------------------------
extern "C" void kernel_launch(void* const* d_in, const int* in_sizes, int n_in,
                              void* d_out, int out_size)
{
    const float* x   = (const float*)d_in[0];
    const float* w1c = (const float*)d_in[1];
    const float* b1c = (const float*)d_in[2];
    const float* w2c = (const float*)d_in[3];
    const float* b2c = (const float*)d_in[4];
    const float* ws1 = (const float*)d_in[5];
    const float* bs1 = (const float*)d_in[6];
    const float* ws2 = (const float*)d_in[7];
    const float* bs2 = (const float*)d_in[8];

    float* out     = (float*)d_out;
    float* out_idx = out;
    float* out_w   = out + (size_t)NTOK * TOPK;
    float* out_m   = out + 2 * (size_t)NTOK * TOPK;
    float* out_c   = out + 3 * (size_t)NTOK * TOPK;

    float *hs_p, *hc_p, *sc_p;
    int *bud_p;
    cudaGetSymbolAddress((void**)&hs_p,  g_hs);
    cudaGetSymbolAddress((void**)&hc_p,  g_hc);
    cudaGetSymbolAddress((void**)&sc_p,  g_scores);
    cudaGetSymbolAddress((void**)&bud_p, g_budget);

    const int TOPK_SMEM = 38912;   // 38 KB dynamic
    static bool attr_set = false;
    if (!attr_set) {
        cudaFuncSetAttribute(topk_kernel,
                             cudaFuncAttributeMaxDynamicSharedMemorySize, TOPK_SMEM);
        attr_set = true;
    }

    small_gemms<<<dim3(3, NTOK / 128), 256>>>(x, ws1, bs1, w1c, b1c, hs_p, hc_p);
    complexity_kernel<<<NTOK / 8, 256>>>(hc_p, w2c, b2c, out_c, bud_p);
    sgemm2_bias<<<dim3(POOL / 128, NTOK / 128), 256>>>(hs_p, ws2, bs2, sc_p, POOL, HID);
    topk_kernel<<<NTOK, 512, TOPK_SMEM>>>(sc_p, bud_p, out_idx, out_w, out_m);
}

// round 16
// speedup vs baseline: 1.0778x; 1.0223x over previous
#include <cuda_runtime.h>
#include <cstdint>
#include <math.h>

#define NTOK 8192
#define DIM  1024
#define HID  256
#define HIDC 128
#define POOL 16384
#define TOPK 1024

// ---------------- scratch (device globals: no allocations allowed) ----------
__device__ float g_hs[NTOK * HID];                              // 8 MB
__device__ float g_hc[NTOK * HIDC];                             // 4 MB
__device__ float g_scores[(size_t)NTOK * POOL];                 // 512 MB
__device__ int   g_budget[NTOK];

// packed fp32x2 FMA (sm_100+): two independent rn-rounded fp32 FMAs per issue.
__device__ __forceinline__ float2 ffma2(float2 a, float2 b, float2 c) {
    unsigned long long A = *(unsigned long long*)&a;
    unsigned long long B = *(unsigned long long*)&b;
    unsigned long long C = *(unsigned long long*)&c;
    unsigned long long D;
    asm("fma.rn.f32x2 %0, %1, %2, %3;" : "=l"(D) : "l"(A), "l"(B), "l"(C));
    return *(float2*)&D;
}

// ---------------- fp32x2 GEMM core (proven R2 version) ----------------------
template<bool RELU>
__device__ __forceinline__ void gemm_body(const float* __restrict__ A,
                                          const float* __restrict__ B,
                                          const float* __restrict__ bias,
                                          float* __restrict__ C,
                                          int N, int K, int bm, int bn,
                                          float Asm[2][8][128], float Bsm[2][8][128])
{
    const int tid = threadIdx.x;
    const int tx  = tid & 15;
    const int ty  = tid >> 4;

    float2 acc[8][4];
#pragma unroll
    for (int i = 0; i < 8; i++)
#pragma unroll
        for (int q = 0; q < 4; q++) acc[i][q] = make_float2(0.f, 0.f);

    const int ar = tid >> 1;
    const int ac = (tid & 1) * 4;
    const int br = tid >> 5;
    const int bc = (tid & 31) * 4;
    const float* Aptr = A + (size_t)(bm + ar) * K + ac;
    const float* Bptr = B + (size_t)br * N + bn + bc;

    const int NT = K >> 3;

    float4 av = *(const float4*)(Aptr);
    float4 bv = *(const float4*)(Bptr);
    Asm[0][ac + 0][ar] = av.x; Asm[0][ac + 1][ar] = av.y;
    Asm[0][ac + 2][ar] = av.z; Asm[0][ac + 3][ar] = av.w;
    *(float4*)&Bsm[0][br][bc] = bv;
    __syncthreads();

    for (int t = 0; t < NT; t++) {
        const int buf = t & 1;
        const bool more = (t + 1) < NT;
        if (more) {
            av = *(const float4*)(Aptr + (t + 1) * 8);
            bv = *(const float4*)(Bptr + (size_t)(t + 1) * 8 * N);
        }

#pragma unroll
        for (int k = 0; k < 8; k++) {
            float4 a0 = *(const float4*)&Asm[buf][k][ty * 8];
            float4 a1 = *(const float4*)&Asm[buf][k][ty * 8 + 4];
            float4 b0 = *(const float4*)&Bsm[buf][k][tx * 4];
            float4 b1 = *(const float4*)&Bsm[buf][k][tx * 4 + 64];
            float2 bp[4];
            bp[0] = make_float2(b0.x, b0.y); bp[1] = make_float2(b0.z, b0.w);
            bp[2] = make_float2(b1.x, b1.y); bp[3] = make_float2(b1.z, b1.w);
            float a[8] = {a0.x, a0.y, a0.z, a0.w, a1.x, a1.y, a1.z, a1.w};
#pragma unroll
            for (int i = 0; i < 8; i++) {
                float2 ad = make_float2(a[i], a[i]);
#pragma unroll
                for (int q = 0; q < 4; q++)
                    acc[i][q] = ffma2(ad, bp[q], acc[i][q]);
            }
        }

        if (more) {
            const int nb = buf ^ 1;
            Asm[nb][ac + 0][ar] = av.x; Asm[nb][ac + 1][ar] = av.y;
            Asm[nb][ac + 2][ar] = av.z; Asm[nb][ac + 3][ar] = av.w;
            *(float4*)&Bsm[nb][br][bc] = bv;
        }
        __syncthreads();
    }

#pragma unroll
    for (int i = 0; i < 8; i++) {
        const int row = bm + ty * 8 + i;
#pragma unroll
        for (int g = 0; g < 2; g++) {
            const int col = bn + tx * 4 + g * 64;
            float4 v;
            v.x = acc[i][g * 2 + 0].x + bias[col + 0];
            v.y = acc[i][g * 2 + 0].y + bias[col + 1];
            v.z = acc[i][g * 2 + 1].x + bias[col + 2];
            v.w = acc[i][g * 2 + 1].y + bias[col + 3];
            if (RELU) {
                v.x = fmaxf(v.x, 0.f); v.y = fmaxf(v.y, 0.f);
                v.z = fmaxf(v.z, 0.f); v.w = fmaxf(v.w, 0.f);
            }
            *(float4*)(C + (size_t)row * N + col) = v;
        }
    }
}

__global__ void __launch_bounds__(256, 2)
sgemm2_bias(const float* __restrict__ A, const float* __restrict__ B,
            const float* __restrict__ bias, float* __restrict__ C,
            int N, int K)
{
    __shared__ float As[2][8][128];
    __shared__ float Bs[2][8][128];
    gemm_body<false>(A, B, bias, C, N, K, blockIdx.y * 128, blockIdx.x * 128, As, Bs);
}

__global__ void __launch_bounds__(256, 2)
small_gemms(const float* __restrict__ x,
            const float* __restrict__ ws1, const float* __restrict__ bs1,
            const float* __restrict__ w1c, const float* __restrict__ b1c,
            float* __restrict__ hs, float* __restrict__ hc)
{
    __shared__ float As[2][8][128];
    __shared__ float Bs[2][8][128];
    const int bx = blockIdx.x;
    if (bx < 2)
        gemm_body<true>(x, ws1, bs1, hs, HID,  DIM, blockIdx.y * 128, bx * 128, As, Bs);
    else
        gemm_body<true>(x, w1c, b1c, hc, HIDC, DIM, blockIdx.y * 128, 0, As, Bs);
}

// ---------------- complexity -> sigmoid -> budget ---------------------------
__global__ void complexity_kernel(const float* __restrict__ hc,
                                  const float* __restrict__ w2c,
                                  const float* __restrict__ b2c,
                                  float* __restrict__ out_c,
                                  int* __restrict__ budget)
{
    int warp = (blockIdx.x * blockDim.x + threadIdx.x) >> 5;
    int lane = threadIdx.x & 31;
    if (warp >= NTOK) return;
    const float* h = hc + (size_t)warp * HIDC;
    float s = 0.f;
#pragma unroll
    for (int i = lane; i < HIDC; i += 32) s += h[i] * w2c[i];
#pragma unroll
    for (int o = 16; o; o >>= 1) s += __shfl_xor_sync(0xFFFFFFFFu, s, o);
    if (lane == 0) {
        float z = s + b2c[0];
        float c = 1.f / (1.f + expf(-z));
        out_c[warp] = c;
        float raw = 100.f + 924.f * (c * c);
        raw = fminf(fmaxf(raw, 100.f), 1024.f);
        budget[warp] = (int)rintf(raw);
    }
}

// ---------------- top-k helpers ---------------------------------------------
__device__ __forceinline__ uint32_t f2mk(float f) {
    uint32_t u = __float_as_uint(f);
    return (u & 0x80000000u) ? ~u : (u | 0x80000000u);
}
__device__ __forceinline__ float mk2f(uint32_t mk) {
    uint32_t u = (mk & 0x80000000u) ? (mk ^ 0x80000000u) : ~mk;
    return __uint_as_float(u);
}

// ---------------- fused top-k: 256 threads, 4 CTAs/SM ------------------------
// smem (dynamic ~35 KB): fin[2048] u64 | hist[4096] u32 | chunksum[256] u32 |
//   warp_aux[32] u32 | s_red[256] f32 | scal[4] u32
__global__ void __launch_bounds__(256, 4)
topk_kernel(const float* __restrict__ scores, const int* __restrict__ budget,
            float* __restrict__ out_idx, float* __restrict__ out_w,
            float* __restrict__ out_m)
{
    extern __shared__ char smem_raw[];
    unsigned long long* fin = (unsigned long long*)smem_raw;
    uint32_t* hist     = (uint32_t*)(fin + 2048);
    uint32_t* chunksum = hist + 4096;
    uint32_t* warp_aux = chunksum + 256;
    float*    s_red    = (float*)(warp_aux + 32);
    uint32_t* scal     = (uint32_t*)(s_red + 256);
    #define S_BSTAR scal[0]
    #define S_CNT   scal[1]
    #define S_END   scal[2]

    const int t    = blockIdx.x;
    const int tid  = threadIdx.x;          // 256 threads, 8 warps
    const int lane = tid & 31;
    const int wid  = tid >> 5;
    const float4* row4 = (const float4*)(scores + (size_t)t * POOL);

    uint32_t cnt = 0, bstar = 0;
    bool     use_sample = true;
    uint32_t target = 192;           // 2048-sample -> expected survivors ~1536

    for (int attempt = 0; attempt < 2; attempt++) {
        for (int i = tid; i < 4096; i += 256) hist[i] = 0;
        if (tid == 0) S_CNT = 0;
        __syncthreads();

        // coarse (12-bit) histogram: contiguous 2048-sample or exact full row
        if (use_sample) {
#pragma unroll
            for (int s = 0; s < 2; s++) {
                float4 v = row4[tid + s * 256];
                atomicAdd(&hist[f2mk(v.x) >> 20], 1u);
                atomicAdd(&hist[f2mk(v.y) >> 20], 1u);
                atomicAdd(&hist[f2mk(v.z) >> 20], 1u);
                atomicAdd(&hist[f2mk(v.w) >> 20], 1u);
            }
        } else {
#pragma unroll
            for (int s = 0; s < 16; s++) {
                float4 v = row4[tid + s * 256];
                atomicAdd(&hist[f2mk(v.x) >> 20], 1u);
                atomicAdd(&hist[f2mk(v.y) >> 20], 1u);
                atomicAdd(&hist[f2mk(v.z) >> 20], 1u);
                atomicAdd(&hist[f2mk(v.w) >> 20], 1u);
            }
        }
        __syncthreads();

        // suffix scan over 256 chunk sums (warp shuffles, 8 warps)
        {
            uint32_t v;
            {
                uint32_t cs = 0;
#pragma unroll
                for (int b = tid * 16; b < tid * 16 + 16; b++) cs += hist[b];
                v = cs;
#pragma unroll
                for (int o = 1; o < 32; o <<= 1) {
                    uint32_t u = __shfl_down_sync(0xFFFFFFFFu, v, o);
                    if (lane + o < 32) v += u;
                }
                if (lane == 0) warp_aux[wid] = v;
            }
            __syncthreads();
            if (tid < 8) {
                uint32_t w = warp_aux[tid];
                uint32_t incl = w;
#pragma unroll
                for (int o = 1; o < 8; o <<= 1) {
                    uint32_t u = __shfl_down_sync(0xFFu, incl, o);
                    if (tid + o < 8) incl += u;
                }
                warp_aux[8 + tid] = incl - w;
            }
            __syncthreads();
            chunksum[tid] = v + warp_aux[8 + wid];
            __syncthreads();
        }

        // crossing chunk -> threshold bin bstar
        {
            uint32_t Sc = chunksum[tid];
            uint32_t Sn = (tid < 255) ? chunksum[tid + 1] : 0;
            if (Sc >= target && Sn < target) {
                uint32_t cum = Sn;
                int b;
                for (b = tid * 16 + 15; b > tid * 16; b--) {
                    cum += hist[b];
                    if (cum >= target) break;
                }
                S_BSTAR = (uint32_t)b;
            }
        }
        __syncthreads();
        bstar = S_BSTAR;

        const uint32_t thrkey = bstar << 20;
        const float    thrF   = mk2f(thrkey);
        const bool     fok    = (bstar > 2049u);

        // clear hist for reuse as FINE histogram
        for (int i = tid; i < 4096; i += 256) hist[i] = 0;
        __syncthreads();

        // pass A: count survivors + fine histogram (64 elems/thread, MLP 4)
        uint32_t c = 0;
#pragma unroll
        for (int h = 0; h < 4; h++) {
            float4 vv[4];
#pragma unroll
            for (int s = 0; s < 4; s++) vv[s] = row4[tid + (h * 4 + s) * 256];
#pragma unroll
            for (int s = 0; s < 4; s++) {
                float vals[4] = {vv[s].x, vv[s].y, vv[s].z, vv[s].w};
#pragma unroll
                for (int e = 0; e < 4; e++) {
                    bool pred = fok ? (vals[e] >= thrF)
                                    : (f2mk(vals[e]) >= thrkey);
                    if (pred) {
                        c++;
                        uint32_t rel = f2mk(vals[e]) - thrkey;
                        uint32_t fb  = rel >> 13;
                        if (fb > 4095u) fb = 4095u;
                        atomicAdd(&hist[fb], 1u);
                    }
                }
            }
        }
#pragma unroll
        for (int o = 16; o; o >>= 1) c += __shfl_xor_sync(0xFFFFFFFFu, c, o);
        if (lane == 0) atomicAdd(&S_CNT, c);
        __syncthreads();
        cnt = S_CNT;
        if (cnt >= (uint32_t)TOPK && cnt <= 2048u) break;
        use_sample = false;
        target = TOPK;
        __syncthreads();
    }
    if (cnt > 2048u) cnt = 2048u;
    const uint32_t thrkey = bstar << 20;
    const float    thrF   = mk2f(thrkey);
    const bool     fok    = (bstar > 2049u);

    // suffix scan fine hist -> per-bin scatter bases (desc order)
    {
        uint32_t v;
        {
            uint32_t cs = 0;
#pragma unroll
            for (int b = tid * 16; b < tid * 16 + 16; b++) cs += hist[b];
            v = cs;
#pragma unroll
            for (int o = 1; o < 32; o <<= 1) {
                uint32_t u = __shfl_down_sync(0xFFFFFFFFu, v, o);
                if (lane + o < 32) v += u;
            }
            if (lane == 0) warp_aux[wid] = v;
        }
        __syncthreads();
        if (tid < 8) {
            uint32_t w = warp_aux[tid];
            uint32_t incl2 = w;
#pragma unroll
            for (int o = 1; o < 8; o <<= 1) {
                uint32_t u = __shfl_down_sync(0xFFu, incl2, o);
                if (tid + o < 8) incl2 += u;
            }
            warp_aux[8 + tid] = incl2 - w;
        }
        __syncthreads();
        chunksum[tid] = v + warp_aux[8 + wid];
        if (tid == 0) S_END = cnt;
        __syncthreads();
    }
    {
        uint32_t acc = (tid < 255) ? chunksum[tid + 1] : 0;
        for (int b = tid * 16 + 15; b >= tid * 16; b--) {
            uint32_t c2 = hist[b];
            hist[b] = acc;          // base for bin b = count in bins > b
            acc += c2;
        }
    }
    __syncthreads();

    // end = min{ base[fb] : base >= 1024 }  (warp min + one atomicMin)
    {
        uint32_t lmin = cnt;
#pragma unroll
        for (int s = 0; s < 16; s++) {
            uint32_t b = hist[tid + s * 256];
            if (b >= (uint32_t)TOPK && b < lmin) lmin = b;
        }
#pragma unroll
        for (int o = 16; o; o >>= 1) {
            uint32_t u = __shfl_xor_sync(0xFFFFFFFFu, lmin, o);
            if (u < lmin) lmin = u;
        }
        if (lane == 0) atomicMin((int*)&S_END, (int)lmin);
        __syncthreads();
    }
    int end = (int)S_END;
    if (end > 2048) end = 2048;
    __syncthreads();

    // pass B: re-read row (cache-hot), scatter survivors directly into fin
#pragma unroll
    for (int h = 0; h < 4; h++) {
        float4 vv[4];
#pragma unroll
        for (int s = 0; s < 4; s++) vv[s] = row4[tid + (h * 4 + s) * 256];
#pragma unroll
        for (int s = 0; s < 4; s++) {
            const int i4 = tid + (h * 4 + s) * 256;
            float vals[4] = {vv[s].x, vv[s].y, vv[s].z, vv[s].w};
#pragma unroll
            for (int e = 0; e < 4; e++) {
                bool pred = fok ? (vals[e] >= thrF)
                                : (f2mk(vals[e]) >= thrkey);
                if (pred) {
                    uint32_t mk  = f2mk(vals[e]);
                    uint32_t rel = mk - thrkey;
                    uint32_t fb  = rel >> 13;
                    if (fb > 4095u) fb = 4095u;
                    if (hist[fb] < (uint32_t)end) {
                        uint32_t p = atomicAdd(&hist[fb], 1u);
                        uint32_t idx = (uint32_t)(i4 * 4 + e);
                        fin[p] = ((unsigned long long)mk << 32) |
                                 (unsigned long long)(0xFFFFFFFFu - idx);
                    }
                }
            }
        }
    }
    __syncthreads();

    // odd-even transposition over [0, end) until sorted (intra-bin fixup)
    while (true) {
        int moved = 0;
#pragma unroll
        for (int r = 0; r < 4; r++) {
            int i = tid + r * 256;
            int p = 2 * i;
            if (p + 1 < end) {
                unsigned long long a = fin[p], b = fin[p + 1];
                if (a < b) { fin[p] = b; fin[p + 1] = a; moved = 1; }
            }
        }
        __syncthreads();
#pragma unroll
        for (int r = 0; r < 4; r++) {
            int i = tid + r * 256;
            int p = 2 * i + 1;
            if (p + 1 < end) {
                unsigned long long a = fin[p], b = fin[p + 1];
                if (a < b) { fin[p] = b; fin[p + 1] = a; moved = 1; }
            }
        }
        if (!__syncthreads_or(moved)) break;
    }

    // softmax over sorted top-1024 + budget mask
    const float vmax = mk2f((uint32_t)(fin[0] >> 32));
    unsigned long long pv[4];
    float ev[4];
    float psum = 0.f;
#pragma unroll
    for (int r = 0; r < 4; r++) {
        pv[r] = fin[tid + r * 256];
        ev[r] = expf(mk2f((uint32_t)(pv[r] >> 32)) - vmax);
        psum += ev[r];
    }
    s_red[tid] = psum;
    __syncthreads();
    for (int o = 128; o; o >>= 1) {
        if (tid < o) s_red[tid] += s_red[tid + o];
        __syncthreads();
    }
    const float inv = 1.f / s_red[0];

    const int bud = budget[t];
    const size_t base = (size_t)t * TOPK;
#pragma unroll
    for (int r = 0; r < 4; r++) {
        int jj = tid + r * 256;
        uint32_t idx = 0xFFFFFFFFu - (uint32_t)(pv[r] & 0xFFFFFFFFull);
        float m = (jj < bud) ? 1.f : 0.f;
        out_idx[base + jj] = (float)idx;
        out_w[base + jj]   = ev[r] * inv * m;
        out_m[base + jj]   = m;
    }
    #undef S_BSTAR
    #undef S_CNT
    #undef S_END
}

// ---------------- launch: serial ----------------------------------------------
extern "C" void kernel_launch(void* const* d_in, const int* in_sizes, int n_in,
                              void* d_out, int out_size)
{
    const float* x   = (const float*)d_in[0];
    const float* w1c = (const float*)d_in[1];
    const float* b1c = (const float*)d_in[2];
    const float* w2c = (const float*)d_in[3];
    const float* b2c = (const float*)d_in[4];
    const float* ws1 = (const float*)d_in[5];
    const float* bs1 = (const float*)d_in[6];
    const float* ws2 = (const float*)d_in[7];
    const float* bs2 = (const float*)d_in[8];

    float* out     = (float*)d_out;
    float* out_idx = out;
    float* out_w   = out + (size_t)NTOK * TOPK;
    float* out_m   = out + 2 * (size_t)NTOK * TOPK;
    float* out_c   = out + 3 * (size_t)NTOK * TOPK;

    float *hs_p, *hc_p, *sc_p;
    int *bud_p;
    cudaGetSymbolAddress((void**)&hs_p,  g_hs);
    cudaGetSymbolAddress((void**)&hc_p,  g_hc);
    cudaGetSymbolAddress((void**)&sc_p,  g_scores);
    cudaGetSymbolAddress((void**)&bud_p, g_budget);

    const int TOPK_SMEM = 35840;   // 35 KB dynamic
    static bool attr_set = false;
    if (!attr_set) {
        cudaFuncSetAttribute(topk_kernel,
                             cudaFuncAttributeMaxDynamicSharedMemorySize, TOPK_SMEM);
        attr_set = true;
    }

    small_gemms<<<dim3(3, NTOK / 128), 256>>>(x, ws1, bs1, w1c, b1c, hs_p, hc_p);
    complexity_kernel<<<NTOK / 8, 256>>>(hc_p, w2c, b2c, out_c, bud_p);
    sgemm2_bias<<<dim3(POOL / 128, NTOK / 128), 256>>>(hs_p, ws2, bs2, sc_p, POOL, HID);
    topk_kernel<<<NTOK, 256, TOPK_SMEM>>>(sc_p, bud_p, out_idx, out_w, out_m);
}

// round 17
// speedup vs baseline: 1.0915x; 1.0127x over previous
#include <cuda_runtime.h>
#include <cstdint>
#include <math.h>

#define NTOK 8192
#define DIM  1024
#define HID  256
#define HIDC 128
#define POOL 16384
#define TOPK 1024

// ---------------- scratch (device globals: no allocations allowed) ----------
__device__ float g_hs[NTOK * HID];                              // 8 MB
__device__ uint32_t g_keys[(size_t)NTOK * POOL];                // 512 MB (monotonic keys)
__device__ int   g_budget[NTOK];

// monotonic float->uint key (order-preserving bijection)
__device__ __forceinline__ uint32_t f2mk(float f) {
    uint32_t u = __float_as_uint(f);
    return (u & 0x80000000u) ? ~u : (u | 0x80000000u);
}
__device__ __forceinline__ float mk2f(uint32_t mk) {
    uint32_t u = (mk & 0x80000000u) ? (mk ^ 0x80000000u) : ~mk;
    return __uint_as_float(u);
}

// packed fp32x2 FMA (sm_100+): two independent rn-rounded fp32 FMAs per issue.
__device__ __forceinline__ float2 ffma2(float2 a, float2 b, float2 c) {
    unsigned long long A = *(unsigned long long*)&a;
    unsigned long long B = *(unsigned long long*)&b;
    unsigned long long C = *(unsigned long long*)&c;
    unsigned long long D;
    asm("fma.rn.f32x2 %0, %1, %2, %3;" : "=l"(D) : "l"(A), "l"(B), "l"(C));
    return *(float2*)&D;
}

// ---------------- fp32x2 GEMM core (proven R2 version) ----------------------
// KEYOUT: store f2mk(value) as u32 keys. COMPLEX: don't store C; instead
// compute complexity = sigmoid(row . w2c + b2c) and budgets in-epilogue.
template<bool RELU, bool KEYOUT, bool COMPLEX>
__device__ __forceinline__ void gemm_body(const float* __restrict__ A,
                                          const float* __restrict__ B,
                                          const float* __restrict__ bias,
                                          float* __restrict__ C,
                                          int N, int K, int bm, int bn,
                                          float Asm[2][8][128], float Bsm[2][8][128],
                                          const float* __restrict__ w2c = nullptr,
                                          const float* __restrict__ b2c = nullptr,
                                          float* __restrict__ out_c = nullptr,
                                          int* __restrict__ budget = nullptr)
{
    const int tid = threadIdx.x;
    const int tx  = tid & 15;
    const int ty  = tid >> 4;

    float2 acc[8][4];
#pragma unroll
    for (int i = 0; i < 8; i++)
#pragma unroll
        for (int q = 0; q < 4; q++) acc[i][q] = make_float2(0.f, 0.f);

    const int ar = tid >> 1;
    const int ac = (tid & 1) * 4;
    const int br = tid >> 5;
    const int bc = (tid & 31) * 4;
    const float* Aptr = A + (size_t)(bm + ar) * K + ac;
    const float* Bptr = B + (size_t)br * N + bn + bc;

    const int NT = K >> 3;

    float4 av = *(const float4*)(Aptr);
    float4 bv = *(const float4*)(Bptr);
    Asm[0][ac + 0][ar] = av.x; Asm[0][ac + 1][ar] = av.y;
    Asm[0][ac + 2][ar] = av.z; Asm[0][ac + 3][ar] = av.w;
    *(float4*)&Bsm[0][br][bc] = bv;
    __syncthreads();

    for (int t = 0; t < NT; t++) {
        const int buf = t & 1;
        const bool more = (t + 1) < NT;
        if (more) {
            av = *(const float4*)(Aptr + (t + 1) * 8);
            bv = *(const float4*)(Bptr + (size_t)(t + 1) * 8 * N);
        }

#pragma unroll
        for (int k = 0; k < 8; k++) {
            float4 a0 = *(const float4*)&Asm[buf][k][ty * 8];
            float4 a1 = *(const float4*)&Asm[buf][k][ty * 8 + 4];
            float4 b0 = *(const float4*)&Bsm[buf][k][tx * 4];
            float4 b1 = *(const float4*)&Bsm[buf][k][tx * 4 + 64];
            float2 bp[4];
            bp[0] = make_float2(b0.x, b0.y); bp[1] = make_float2(b0.z, b0.w);
            bp[2] = make_float2(b1.x, b1.y); bp[3] = make_float2(b1.z, b1.w);
            float a[8] = {a0.x, a0.y, a0.z, a0.w, a1.x, a1.y, a1.z, a1.w};
#pragma unroll
            for (int i = 0; i < 8; i++) {
                float2 ad = make_float2(a[i], a[i]);
#pragma unroll
                for (int q = 0; q < 4; q++)
                    acc[i][q] = ffma2(ad, bp[q], acc[i][q]);
            }
        }

        if (more) {
            const int nb = buf ^ 1;
            Asm[nb][ac + 0][ar] = av.x; Asm[nb][ac + 1][ar] = av.y;
            Asm[nb][ac + 2][ar] = av.z; Asm[nb][ac + 3][ar] = av.w;
            *(float4*)&Bsm[nb][br][bc] = bv;
        }
        __syncthreads();
    }

    float part[8];
    if (COMPLEX) {
#pragma unroll
        for (int i = 0; i < 8; i++) part[i] = 0.f;
    }

#pragma unroll
    for (int i = 0; i < 8; i++) {
        const int row = bm + ty * 8 + i;
#pragma unroll
        for (int g = 0; g < 2; g++) {
            const int col = bn + tx * 4 + g * 64;
            float v[4];
            v[0] = acc[i][g * 2 + 0].x + bias[col + 0];
            v[1] = acc[i][g * 2 + 0].y + bias[col + 1];
            v[2] = acc[i][g * 2 + 1].x + bias[col + 2];
            v[3] = acc[i][g * 2 + 1].y + bias[col + 3];
            if (RELU) {
#pragma unroll
                for (int j = 0; j < 4; j++) v[j] = fmaxf(v[j], 0.f);
            }
            if (COMPLEX) {
#pragma unroll
                for (int j = 0; j < 4; j++)
                    part[i] += v[j] * w2c[col + j];
            } else if (KEYOUT) {
                uint32_t kk[4];
#pragma unroll
                for (int j = 0; j < 4; j++) kk[j] = f2mk(v[j]);
                *(uint4*)((uint32_t*)C + (size_t)row * N + col) =
                    make_uint4(kk[0], kk[1], kk[2], kk[3]);
            } else {
                *(float4*)(C + (size_t)row * N + col) =
                    make_float4(v[0], v[1], v[2], v[3]);
            }
        }
    }

    if (COMPLEX) {
        // reduce across the 16 threads sharing ty (lanes form a 16-aligned group)
#pragma unroll
        for (int i = 0; i < 8; i++) {
#pragma unroll
            for (int o = 1; o < 16; o <<= 1)
                part[i] += __shfl_xor_sync(0xFFFFFFFFu, part[i], o);
        }
        if (tx == 0) {
#pragma unroll
            for (int i = 0; i < 8; i++) {
                const int row = bm + ty * 8 + i;
                float z = part[i] + b2c[0];
                float c = 1.f / (1.f + expf(-z));
                out_c[row] = c;
                float raw = 100.f + 924.f * (c * c);
                raw = fminf(fmaxf(raw, 100.f), 1024.f);
                budget[row] = (int)rintf(raw);
            }
        }
    }
}

// GEMM2: keys = f2mk(hs @ ws2 + bs2)
__global__ void __launch_bounds__(256, 2)
sgemm2_bias(const float* __restrict__ A, const float* __restrict__ B,
            const float* __restrict__ bias, float* __restrict__ C,
            int N, int K)
{
    __shared__ float As[2][8][128];
    __shared__ float Bs[2][8][128];
    gemm_body<false, true, false>(A, B, bias, C, N, K,
                                  blockIdx.y * 128, blockIdx.x * 128, As, Bs);
}

// fused: bx<2 -> hs tile; bx==2 -> hc tile + in-epilogue complexity/budgets
__global__ void __launch_bounds__(256, 2)
small_gemms(const float* __restrict__ x,
            const float* __restrict__ ws1, const float* __restrict__ bs1,
            const float* __restrict__ w1c, const float* __restrict__ b1c,
            const float* __restrict__ w2c, const float* __restrict__ b2c,
            float* __restrict__ hs, float* __restrict__ out_c,
            int* __restrict__ budget)
{
    __shared__ float As[2][8][128];
    __shared__ float Bs[2][8][128];
    const int bx = blockIdx.x;
    if (bx < 2)
        gemm_body<true, false, false>(x, ws1, bs1, hs, HID, DIM,
                                      blockIdx.y * 128, bx * 128, As, Bs);
    else
        gemm_body<true, false, true>(x, w1c, b1c, nullptr, HIDC, DIM,
                                     blockIdx.y * 128, 0, As, Bs,
                                     w2c, b2c, out_c, budget);
}

// ---------------- fused top-k: pure-integer keys, 256 thr, 4 CTAs/SM --------
// smem (dynamic ~35 KB): fin[2048] u64 | hist[4096] u32 | chunksum[256] u32 |
//   warp_aux[32] u32 | s_red[256] f32 | scal[4] u32
__global__ void __launch_bounds__(256, 4)
topk_kernel(const uint32_t* __restrict__ keys, const int* __restrict__ budget,
            float* __restrict__ out_idx, float* __restrict__ out_w,
            float* __restrict__ out_m)
{
    extern __shared__ char smem_raw[];
    unsigned long long* fin = (unsigned long long*)smem_raw;
    uint32_t* hist     = (uint32_t*)(fin + 2048);
    uint32_t* chunksum = hist + 4096;
    uint32_t* warp_aux = chunksum + 256;
    float*    s_red    = (float*)(warp_aux + 32);
    uint32_t* scal     = (uint32_t*)(s_red + 256);
    #define S_BSTAR scal[0]
    #define S_CNT   scal[1]
    #define S_END   scal[2]

    const int t    = blockIdx.x;
    const int tid  = threadIdx.x;          // 256 threads, 8 warps
    const int lane = tid & 31;
    const int wid  = tid >> 5;
    const uint4* row4 = (const uint4*)(keys + (size_t)t * POOL);

    uint32_t cnt = 0, bstar = 0;
    bool     use_sample = true;
    uint32_t target = 192;           // 2048-sample -> expected survivors ~1536

    for (int attempt = 0; attempt < 2; attempt++) {
        for (int i = tid; i < 4096; i += 256) hist[i] = 0;
        if (tid == 0) S_CNT = 0;
        __syncthreads();

        // coarse (12-bit) histogram: contiguous 2048-sample or exact full row
        if (use_sample) {
#pragma unroll
            for (int s = 0; s < 2; s++) {
                uint4 v = row4[tid + s * 256];
                atomicAdd(&hist[v.x >> 20], 1u);
                atomicAdd(&hist[v.y >> 20], 1u);
                atomicAdd(&hist[v.z >> 20], 1u);
                atomicAdd(&hist[v.w >> 20], 1u);
            }
        } else {
#pragma unroll
            for (int s = 0; s < 16; s++) {
                uint4 v = row4[tid + s * 256];
                atomicAdd(&hist[v.x >> 20], 1u);
                atomicAdd(&hist[v.y >> 20], 1u);
                atomicAdd(&hist[v.z >> 20], 1u);
                atomicAdd(&hist[v.w >> 20], 1u);
            }
        }
        __syncthreads();

        // suffix scan over 256 chunk sums (warp shuffles, 8 warps)
        {
            uint32_t v;
            {
                uint32_t cs = 0;
#pragma unroll
                for (int b = tid * 16; b < tid * 16 + 16; b++) cs += hist[b];
                v = cs;
#pragma unroll
                for (int o = 1; o < 32; o <<= 1) {
                    uint32_t u = __shfl_down_sync(0xFFFFFFFFu, v, o);
                    if (lane + o < 32) v += u;
                }
                if (lane == 0) warp_aux[wid] = v;
            }
            __syncthreads();
            if (tid < 8) {
                uint32_t w = warp_aux[tid];
                uint32_t incl = w;
#pragma unroll
                for (int o = 1; o < 8; o <<= 1) {
                    uint32_t u = __shfl_down_sync(0xFFu, incl, o);
                    if (tid + o < 8) incl += u;
                }
                warp_aux[8 + tid] = incl - w;
            }
            __syncthreads();
            chunksum[tid] = v + warp_aux[8 + wid];
            __syncthreads();
        }

        // crossing chunk -> threshold bin bstar
        {
            uint32_t Sc = chunksum[tid];
            uint32_t Sn = (tid < 255) ? chunksum[tid + 1] : 0;
            if (Sc >= target && Sn < target) {
                uint32_t cum = Sn;
                int b;
                for (b = tid * 16 + 15; b > tid * 16; b--) {
                    cum += hist[b];
                    if (cum >= target) break;
                }
                S_BSTAR = (uint32_t)b;
            }
        }
        __syncthreads();
        bstar = S_BSTAR;
        const uint32_t thrkey = bstar << 20;

        // clear hist for reuse as FINE histogram
        for (int i = tid; i < 4096; i += 256) hist[i] = 0;
        __syncthreads();

        // pass A: count survivors + fine histogram (pure integer compares)
        uint32_t c = 0;
#pragma unroll
        for (int h = 0; h < 4; h++) {
            uint4 vv[4];
#pragma unroll
            for (int s = 0; s < 4; s++) vv[s] = row4[tid + (h * 4 + s) * 256];
#pragma unroll
            for (int s = 0; s < 4; s++) {
                uint32_t vals[4] = {vv[s].x, vv[s].y, vv[s].z, vv[s].w};
#pragma unroll
                for (int e = 0; e < 4; e++) {
                    if (vals[e] >= thrkey) {
                        c++;
                        uint32_t fb = (vals[e] - thrkey) >> 13;
                        if (fb > 4095u) fb = 4095u;
                        atomicAdd(&hist[fb], 1u);
                    }
                }
            }
        }
#pragma unroll
        for (int o = 16; o; o >>= 1) c += __shfl_xor_sync(0xFFFFFFFFu, c, o);
        if (lane == 0) atomicAdd(&S_CNT, c);
        __syncthreads();
        cnt = S_CNT;
        if (cnt >= (uint32_t)TOPK && cnt <= 2048u) break;
        use_sample = false;
        target = TOPK;
        __syncthreads();
    }
    if (cnt > 2048u) cnt = 2048u;
    const uint32_t thrkey = bstar << 20;

    // suffix scan fine hist -> per-bin scatter bases (desc order)
    {
        uint32_t v;
        {
            uint32_t cs = 0;
#pragma unroll
            for (int b = tid * 16; b < tid * 16 + 16; b++) cs += hist[b];
            v = cs;
#pragma unroll
            for (int o = 1; o < 32; o <<= 1) {
                uint32_t u = __shfl_down_sync(0xFFFFFFFFu, v, o);
                if (lane + o < 32) v += u;
            }
            if (lane == 0) warp_aux[wid] = v;
        }
        __syncthreads();
        if (tid < 8) {
            uint32_t w = warp_aux[tid];
            uint32_t incl2 = w;
#pragma unroll
            for (int o = 1; o < 8; o <<= 1) {
                uint32_t u = __shfl_down_sync(0xFFu, incl2, o);
                if (tid + o < 8) incl2 += u;
            }
            warp_aux[8 + tid] = incl2 - w;
        }
        __syncthreads();
        chunksum[tid] = v + warp_aux[8 + wid];
        if (tid == 0) S_END = cnt;
        __syncthreads();
    }
    {
        uint32_t acc = (tid < 255) ? chunksum[tid + 1] : 0;
        for (int b = tid * 16 + 15; b >= tid * 16; b--) {
            uint32_t c2 = hist[b];
            hist[b] = acc;          // base for bin b = count in bins > b
            acc += c2;
        }
    }
    __syncthreads();

    // end = min{ base[fb] : base >= 1024 }
    {
        uint32_t lmin = cnt;
#pragma unroll
        for (int s = 0; s < 16; s++) {
            uint32_t b = hist[tid + s * 256];
            if (b >= (uint32_t)TOPK && b < lmin) lmin = b;
        }
#pragma unroll
        for (int o = 16; o; o >>= 1) {
            uint32_t u = __shfl_xor_sync(0xFFFFFFFFu, lmin, o);
            if (u < lmin) lmin = u;
        }
        if (lane == 0) atomicMin((int*)&S_END, (int)lmin);
        __syncthreads();
    }
    int end = (int)S_END;
    if (end > 2048) end = 2048;
    __syncthreads();

    // pass B: re-read row (cache-hot), scatter survivors directly into fin
#pragma unroll
    for (int h = 0; h < 4; h++) {
        uint4 vv[4];
#pragma unroll
        for (int s = 0; s < 4; s++) vv[s] = row4[tid + (h * 4 + s) * 256];
#pragma unroll
        for (int s = 0; s < 4; s++) {
            const int i4 = tid + (h * 4 + s) * 256;
            uint32_t vals[4] = {vv[s].x, vv[s].y, vv[s].z, vv[s].w};
#pragma unroll
            for (int e = 0; e < 4; e++) {
                if (vals[e] >= thrkey) {
                    uint32_t fb = (vals[e] - thrkey) >> 13;
                    if (fb > 4095u) fb = 4095u;
                    if (hist[fb] < (uint32_t)end) {
                        uint32_t p = atomicAdd(&hist[fb], 1u);
                        uint32_t idx = (uint32_t)(i4 * 4 + e);
                        fin[p] = ((unsigned long long)vals[e] << 32) |
                                 (unsigned long long)(0xFFFFFFFFu - idx);
                    }
                }
            }
        }
    }
    __syncthreads();

    // odd-even transposition over [0, end) until sorted (intra-bin fixup)
    while (true) {
        int moved = 0;
#pragma unroll
        for (int r = 0; r < 4; r++) {
            int i = tid + r * 256;
            int p = 2 * i;
            if (p + 1 < end) {
                unsigned long long a = fin[p], b = fin[p + 1];
                if (a < b) { fin[p] = b; fin[p + 1] = a; moved = 1; }
            }
        }
        __syncthreads();
#pragma unroll
        for (int r = 0; r < 4; r++) {
            int i = tid + r * 256;
            int p = 2 * i + 1;
            if (p + 1 < end) {
                unsigned long long a = fin[p], b = fin[p + 1];
                if (a < b) { fin[p] = b; fin[p + 1] = a; moved = 1; }
            }
        }
        if (!__syncthreads_or(moved)) break;
    }

    // softmax over sorted top-1024 + budget mask
    const float vmax = mk2f((uint32_t)(fin[0] >> 32));
    unsigned long long pv[4];
    float ev[4];
    float psum = 0.f;
#pragma unroll
    for (int r = 0; r < 4; r++) {
        pv[r] = fin[tid + r * 256];
        ev[r] = expf(mk2f((uint32_t)(pv[r] >> 32)) - vmax);
        psum += ev[r];
    }
    s_red[tid] = psum;
    __syncthreads();
    for (int o = 128; o; o >>= 1) {
        if (tid < o) s_red[tid] += s_red[tid + o];
        __syncthreads();
    }
    const float inv = 1.f / s_red[0];

    const int bud = budget[t];
    const size_t base = (size_t)t * TOPK;
#pragma unroll
    for (int r = 0; r < 4; r++) {
        int jj = tid + r * 256;
        uint32_t idx = 0xFFFFFFFFu - (uint32_t)(pv[r] & 0xFFFFFFFFull);
        float m = (jj < bud) ? 1.f : 0.f;
        out_idx[base + jj] = (float)idx;
        out_w[base + jj]   = ev[r] * inv * m;
        out_m[base + jj]   = m;
    }
    #undef S_BSTAR
    #undef S_CNT
    #undef S_END
}

// ---------------- launch: serial ----------------------------------------------
extern "C" void kernel_launch(void* const* d_in, const int* in_sizes, int n_in,
                              void* d_out, int out_size)
{
    const float* x   = (const float*)d_in[0];
    const float* w1c = (const float*)d_in[1];
    const float* b1c = (const float*)d_in[2];
    const float* w2c = (const float*)d_in[3];
    const float* b2c = (const float*)d_in[4];
    const float* ws1 = (const float*)d_in[5];
    const float* bs1 = (const float*)d_in[6];
    const float* ws2 = (const float*)d_in[7];
    const float* bs2 = (const float*)d_in[8];

    float* out     = (float*)d_out;
    float* out_idx = out;
    float* out_w   = out + (size_t)NTOK * TOPK;
    float* out_m   = out + 2 * (size_t)NTOK * TOPK;
    float* out_c   = out + 3 * (size_t)NTOK * TOPK;

    float *hs_p;
    uint32_t *key_p;
    int *bud_p;
    cudaGetSymbolAddress((void**)&hs_p,  g_hs);
    cudaGetSymbolAddress((void**)&key_p, g_keys);
    cudaGetSymbolAddress((void**)&bud_p, g_budget);

    const int TOPK_SMEM = 35840;   // 35 KB dynamic
    static bool attr_set = false;
    if (!attr_set) {
        cudaFuncSetAttribute(topk_kernel,
                             cudaFuncAttributeMaxDynamicSharedMemorySize, TOPK_SMEM);
        attr_set = true;
    }

    // hs GEMM + (hc GEMM fused with complexity/budget)
    small_gemms<<<dim3(3, NTOK / 128), 256>>>(x, ws1, bs1, w1c, b1c,
                                              w2c, b2c, hs_p, out_c, bud_p);
    // keys = f2mk(hs @ ws2 + bs2)
    sgemm2_bias<<<dim3(POOL / 128, NTOK / 128), 256>>>(hs_p, ws2, bs2,
                                                       (float*)key_p, POOL, HID);
    // integer-domain top-k + softmax + mask
    topk_kernel<<<NTOK, 256, TOPK_SMEM>>>(key_p, bud_p, out_idx, out_w, out_m);
}